// round 9
// baseline (speedup 1.0000x reference)
#include <cuda_runtime.h>
#include <cuda_bf16.h>
#include <stdint.h>

#define BATCH 16384
#define DIMQ  512
#define ZPD   1024
#define HID   256
#define DTC   0.1f

#define BM 32
#define XPITCH 528                        // 256 bf16 = 512B + 16B pad (ldsm conflict-free)
#define X_OFF 0                           // h1, then d1 (in-place)
#define XSZ (BM * XPITCH)                 // 16896
#define Y_OFF XSZ                         // d2; stage-1 A staging overlay (6 x 2560 = 15360)
#define ASLOT 2560                        // 32 rows x 80B
#define WB_OFF (2 * XSZ)                  // 33792: per-warp B buffers
#define WBUF 2560                         // 32 rows x 80B
#define SMEM_SZ (WB_OFF + 8 * 2 * WBUF)   // 74752 -> 3 CTAs/SM

// ---------------- device globals (no allocs allowed) ----------------
__device__ float         g_zp [BATCH * ZPD];     // fp32 master [q|p]
__device__ __nv_bfloat16 g_zpb[BATCH * ZPD];     // bf16 mirror (MMA operand)
__device__ __nv_bfloat16 g_W1t[HID * ZPD];       // W1^T [256][1024]
__device__ __nv_bfloat16 g_W1d[ZPD * HID];       // W1   [1024][256]
__device__ __nv_bfloat16 g_W2t[HID * HID];       // W2^T
__device__ __nv_bfloat16 g_W2d[HID * HID];       // W2

// ---------------- helpers ----------------
__device__ __forceinline__ uint32_t smem_u32(const void* p) {
    uint32_t a;
    asm("{ .reg .u64 t; cvta.to.shared.u64 t, %1; cvt.u32.u64 %0, t; }" : "=r"(a) : "l"(p));
    return a;
}
__device__ __forceinline__ float tanh_fast(float x) {
    float y; asm("tanh.approx.f32 %0, %1;" : "=f"(y) : "f"(x)); return y;
}
__device__ __forceinline__ void cp16(uint32_t s, const void* g) {
    asm volatile("cp.async.cg.shared.global [%0], [%1], 16;" :: "r"(s), "l"(g) : "memory");
}
__device__ __forceinline__ void cp_commit() {
    asm volatile("cp.async.commit_group;" ::: "memory");
}
__device__ __forceinline__ void ldsm4(uint32_t* r, uint32_t a) {
    asm volatile("ldmatrix.sync.aligned.m8n8.x4.shared.b16 {%0,%1,%2,%3}, [%4];"
                 : "=r"(r[0]), "=r"(r[1]), "=r"(r[2]), "=r"(r[3]) : "r"(a));
}
__device__ __forceinline__ void mma16816(float* c, const uint32_t* a, const uint32_t* b) {
    asm volatile("mma.sync.aligned.m16n8k16.row.col.f32.bf16.bf16.f32 "
                 "{%0,%1,%2,%3}, {%4,%5,%6,%7}, {%8,%9}, {%0,%1,%2,%3};"
                 : "+f"(c[0]), "+f"(c[1]), "+f"(c[2]), "+f"(c[3])
                 : "r"(a[0]), "r"(a[1]), "r"(a[2]), "r"(a[3]), "r"(b[0]), "r"(b[1]));
}
__device__ __forceinline__ __nv_bfloat162 pack_bf2(float a, float b) {
    return __halves2bfloat162(__float2bfloat16_rn(a), __float2bfloat16_rn(b));
}

#define ZERO_ACC(acc)                                                           \
    _Pragma("unroll") for (int _i = 0; _i < 2; _i++)                            \
    _Pragma("unroll") for (int _j = 0; _j < 4; _j++)                            \
    _Pragma("unroll") for (int _d = 0; _d < 4; _d++) (acc)[_i][_j][_d] = 0.f;

// consume one k32 chunk: A 32 rows from (abase, apitch), B warp slice (bbase, 80B rows)
__device__ __forceinline__ void consume_k32(
    uint32_t abase, int apitch, uint32_t bbase,
    float (&acc)[2][4][4], int lane)
{
    #pragma unroll
    for (int kt = 0; kt < 2; kt++) {
        uint32_t a[2][4], b[2][4];
        #pragma unroll
        for (int mt = 0; mt < 2; mt++)
            ldsm4(a[mt], abase + (mt * 16 + (lane & 15)) * apitch
                          + ((lane >> 4) << 4) + kt * 32);
        #pragma unroll
        for (int p = 0; p < 2; p++)
            ldsm4(b[p], bbase + (p * 16 + ((lane >> 4) << 3) + (lane & 7)) * 80
                         + (((lane >> 3) & 1) << 4) + kt * 32);
        #pragma unroll
        for (int mt = 0; mt < 2; mt++)
            #pragma unroll
            for (int p = 0; p < 2; p++) {
                mma16816(acc[mt][2 * p],     a[mt], &b[p][0]);
                mma16816(acc[mt][2 * p + 1], a[mt], &b[p][2]);
            }
    }
}

// fill warp-private B slot: 32 weight rows x one k32 chunk (128 16B units, 4/lane)
__device__ __forceinline__ void fillB_warp(uint32_t stg, const __nv_bfloat16* __restrict__ W,
                                           int stride, int n0w, int c, int lane)
{
    #pragma unroll
    for (int r = 0; r < 4; r++) {
        const int u = r * 32 + lane;
        const int row = u >> 2, ch = u & 3;
        cp16(stg + row * 80 + ch * 16, W + (size_t)(n0w + row) * stride + c * 32 + ch * 8);
    }
}

// ---------------------------------------------------------------------------
// Stage 1: acc = zp_tile[32 x 1024] @ W1t^T.
// B: warp-private (W1t n-slice) double buffer.  A: zpb staged 6-deep in Y
// overlay, prefetch distance 4, one __syncthreads per chunk (data pre-landed).
// Commit stream is uniform (2 groups per iter, empty allowed) -> wait_group 2.
// ---------------------------------------------------------------------------
__device__ __forceinline__ void stage1_gemm(
    uint32_t sb, const __nv_bfloat16* __restrict__ Agm,
    float (&acc)[2][4][4], int tid)
{
    const int lane = tid & 31, wn = tid >> 5;
    const uint32_t wb = sb + WB_OFF + wn * 2 * WBUF;
    ZERO_ACC(acc);

    auto fillA = [&](int s, int c) {
        if (tid < 128) {        // 32 rows x 4 x 16B = 128 units
            const int row = tid >> 2, ch = tid & 3;
            cp16(sb + Y_OFF + s * ASLOT + row * 80 + ch * 16,
                 Agm + (size_t)row * ZPD + c * 32 + ch * 8);
        }
    };

    // prologue: A chunks 0..3 in ONE group; B chunk 0 in one group
    fillA(0, 0); fillA(1, 1); fillA(2, 2); fillA(3, 3);
    cp_commit();
    fillB_warp(wb, g_W1t, ZPD, wn * 32, 0, lane);
    cp_commit();

    #pragma unroll 1
    for (int c = 0; c < 32; c++) {
        if (c + 4 < 32) fillA((c + 4) % 6, c + 4);
        cp_commit();
        if (c + 1 < 32) fillB_warp(wb + ((c + 1) & 1) * WBUF, g_W1t, ZPD, wn * 32, c + 1, lane);
        cp_commit();
        asm volatile("cp.async.wait_group 2;" ::: "memory");
        __syncthreads();
        consume_k32(sb + Y_OFF + (c % 6) * ASLOT, 80, wb + (c & 1) * WBUF, acc, lane);
    }
}

// ---------------------------------------------------------------------------
// Stages 2-4: A resident in smem (XPITCH rows), B warp-local double buffer.
// NO CTA barriers.
// ---------------------------------------------------------------------------
__device__ __forceinline__ void gemm_res(
    uint32_t sb, uint32_t aOff, const __nv_bfloat16* __restrict__ W,
    float (&acc)[2][4][4], int lane, int wn)
{
    ZERO_ACC(acc);
    const uint32_t wb = sb + WB_OFF + wn * 2 * WBUF;
    const int n0w = wn * 32;

    fillB_warp(wb, W, HID, n0w, 0, lane);
    cp_commit();
    #pragma unroll 1
    for (int c = 0; c < 8; c++) {
        if (c + 1 < 8) {
            fillB_warp(wb + ((c + 1) & 1) * WBUF, W, HID, n0w, c + 1, lane);
            cp_commit();
            asm volatile("cp.async.wait_group 1;" ::: "memory");
        } else {
            asm volatile("cp.async.wait_group 0;" ::: "memory");
        }
        __syncwarp();
        consume_k32(sb + aOff + c * 64, XPITCH, wb + (c & 1) * WBUF, acc, lane);
    }
}

#define EPI_BEGIN                                                               \
    _Pragma("unroll") for (int mt = 0; mt < 2; mt++)                            \
    _Pragma("unroll") for (int i2 = 0; i2 < 2; i2++) {                          \
        const int m = mt * 16 + i2 * 8 + (lane >> 2);                           \
        _Pragma("unroll") for (int nt = 0; nt < 4; nt++) {                      \
            const int n = wn * 32 + nt * 8 + 2 * (lane & 3);                    \
            const float v0 = acc[mt][nt][i2 * 2], v1 = acc[mt][nt][i2 * 2 + 1];
#define EPI_END }}

// ---------------------------------------------------------------------------
// Mega-kernel: one CTA owns 32 batch rows through ALL 9 gradH calls.
// ---------------------------------------------------------------------------
__global__ void __launch_bounds__(256, 3) leapfrog_all(
    const float* __restrict__ b1, const float* __restrict__ b2,
    const float* __restrict__ W3)
{
    extern __shared__ char smem[];
    const uint32_t sb = smem_u32(smem);
    const int tid = threadIdx.x, lane = tid & 31, wn = tid >> 5;
    const int m0 = blockIdx.x * BM;

    float acc[2][4][4];

    #pragma unroll 1
    for (int it = 0; it < 9; it++) {
        const int call = it - (it / 3) * 3;
        const int qpOff   = (call == 1) ? DIMQ : 0;
        const int colBase = (call == 1) ? 0 : DIMQ;
        const float coef  = (call == 1) ? DTC : -0.5f * DTC;

        // Stage 1: h1 = tanh(zp @ W1 + b1) -> X
        stage1_gemm(sb, g_zpb + (size_t)m0 * ZPD, acc, tid);
        EPI_BEGIN
            const float t0 = tanh_fast(v0 + __ldg(b1 + n));
            const float t1 = tanh_fast(v1 + __ldg(b1 + n + 1));
            *(__nv_bfloat162*)(smem + X_OFF + m * XPITCH + n * 2) = pack_bf2(t0, t1);
        EPI_END
        __syncthreads();

        // Stage 2: d2 = (1 - tanh(h1@W2 + b2)^2) * W3 -> Y
        gemm_res(sb, X_OFF, g_W2t, acc, lane, wn);
        EPI_BEGIN
            const float t0 = tanh_fast(v0 + __ldg(b2 + n));
            const float t1 = tanh_fast(v1 + __ldg(b2 + n + 1));
            const float r0 = (1.0f - t0 * t0) * __ldg(W3 + n);
            const float r1 = (1.0f - t1 * t1) * __ldg(W3 + n + 1);
            *(__nv_bfloat162*)(smem + Y_OFF + m * XPITCH + n * 2) = pack_bf2(r0, r1);
        EPI_END
        __syncthreads();

        // Stage 3: d1 = (d2 @ W2^T) * (1 - h1^2) -> X in-place (owner rmw)
        gemm_res(sb, Y_OFF, g_W2d, acc, lane, wn);
        EPI_BEGIN
            __nv_bfloat162* xp = (__nv_bfloat162*)(smem + X_OFF + m * XPITCH + n * 2);
            const __nv_bfloat162 hh = *xp;
            const float h0 = __bfloat162float(hh.x), h1v = __bfloat162float(hh.y);
            *xp = pack_bf2(v0 * (1.0f - h0 * h0), v1 * (1.0f - h1v * h1v));
        EPI_END
        __syncthreads();

        // Stage 4: g-half = d1 @ W1[qpOff..]^T, fused leapfrog zp update
        #pragma unroll 1
        for (int pass = 0; pass < 2; pass++) {
            gemm_res(sb, X_OFF, g_W1d + (size_t)(qpOff + pass * 256) * HID, acc, lane, wn);
            EPI_BEGIN
                const size_t o = (size_t)(m0 + m) * ZPD + colBase + pass * 256 + n;
                float2 z = *(float2*)(g_zp + o);
                z.x += coef * v0;
                z.y += coef * v1;
                *(float2*)(g_zp + o) = z;
                *(__nv_bfloat162*)(g_zpb + o) = pack_bf2(z.x, z.y);
            EPI_END
        }
        __syncthreads();   // call boundary: zp/zpb visible to next stage 1
    }
}

// ---------------- small kernels ----------------
__global__ void __launch_bounds__(256) prep_weights(const float* __restrict__ W1,
                                                    const float* __restrict__ W2)
{
    const int idx = blockIdx.x * 256 + threadIdx.x;     // 0 .. 262143
    {
        const int k = idx >> 8, n = idx & 255;
        const __nv_bfloat16 v = __float2bfloat16_rn(W1[idx]);
        g_W1d[idx] = v;
        g_W1t[n * ZPD + k] = v;
    }
    if (idx < HID * HID) {
        const int k = idx >> 8, n = idx & 255;
        const __nv_bfloat16 v = __float2bfloat16_rn(W2[idx]);
        g_W2d[idx] = v;
        g_W2t[n * HID + k] = v;
    }
}

__global__ void __launch_bounds__(256) init_zp(const float* __restrict__ z)
{
    const int i = blockIdx.x * 256 + threadIdx.x;       // over BATCH*DIMQ/4
    const int m = i / (DIMQ / 4);
    const int c = (i % (DIMQ / 4)) * 4;
    const float4 zv = *(const float4*)&z[(size_t)m * DIMQ + c];
    const size_t oq = (size_t)m * ZPD + c;
    const size_t op = oq + DIMQ;
    *(float4*)&g_zp[oq] = zv;
    *(float4*)&g_zp[op] = make_float4(0.f, 0.f, 0.f, 0.f);
    __nv_bfloat162 b01 = pack_bf2(zv.x, zv.y), b23 = pack_bf2(zv.z, zv.w);
    *(uint2*)&g_zpb[oq] = make_uint2(*(uint32_t*)&b01, *(uint32_t*)&b23);
    *(uint2*)&g_zpb[op] = make_uint2(0u, 0u);
}

__global__ void __launch_bounds__(256) write_out(float* __restrict__ out)
{
    const int i = blockIdx.x * 256 + threadIdx.x;
    const int m = i / (DIMQ / 4);
    const int c = (i % (DIMQ / 4)) * 4;
    *(float4*)&out[(size_t)m * DIMQ + c] = *(const float4*)&g_zp[(size_t)m * ZPD + c];
}

// ---------------- launcher ----------------
extern "C" void kernel_launch(void* const* d_in, const int* in_sizes, int n_in,
                              void* d_out, int out_size)
{
    const float* z  = (const float*)d_in[0];
    const float* W1 = (const float*)d_in[1];
    const float* b1 = (const float*)d_in[2];
    const float* W2 = (const float*)d_in[3];
    const float* b2 = (const float*)d_in[4];
    const float* W3 = (const float*)d_in[5];
    // d_in[6] = b3: constant, no gradient contribution.
    float* out = (float*)d_out;

    cudaFuncSetAttribute(leapfrog_all, cudaFuncAttributeMaxDynamicSharedMemorySize, SMEM_SZ);

    const dim3 blk(256);
    const dim3 grid_cp((BATCH * DIMQ / 4) / 256);

    init_zp<<<grid_cp, blk>>>(z);
    prep_weights<<<ZPD * HID / 256, blk>>>(W1, W2);
    leapfrog_all<<<BATCH / BM, blk, SMEM_SZ>>>(b1, b2, W3);
    write_out<<<grid_cp, blk>>>(out);
}

// round 10
// speedup vs baseline: 1.3433x; 1.3433x over previous
#include <cuda_runtime.h>
#include <cuda_bf16.h>
#include <stdint.h>

#define BATCH 16384
#define DIMQ  512
#define ZPD   1024
#define HID   256
#define DTC   0.1f

#define BM 64
#define XPITCH 528                        // 256 bf16 = 512B + 16B pad (ldsm conflict-free)
#define X_OFF 0                           // h1, then d1 (in-place)
#define XSZ (BM * XPITCH)                 // 33792
#define Y_OFF XSZ                         // d2; stage-1 A ring overlay (6 x 5120 = 30720)
#define ASLOT 5120                        // 64 rows x 80B
#define WB_OFF (2 * XSZ)                  // 67584: per-warp B buffers
#define WBUF 2560                         // 32 rows x 80B
#define SMEM_SZ (WB_OFF + 8 * 2 * WBUF)   // 108544 -> 2 CTAs/SM

// ---------------- device globals (no allocs allowed) ----------------
__device__ float         g_zp [BATCH * ZPD];     // fp32 master [q|p]
__device__ __nv_bfloat16 g_zpb[BATCH * ZPD];     // bf16 mirror (MMA operand)
__device__ __nv_bfloat16 g_W1t[HID * ZPD];       // W1^T [256][1024]
__device__ __nv_bfloat16 g_W1d[ZPD * HID];       // W1   [1024][256]
__device__ __nv_bfloat16 g_W2t[HID * HID];       // W2^T
__device__ __nv_bfloat16 g_W2d[HID * HID];       // W2

// ---------------- helpers ----------------
__device__ __forceinline__ uint32_t smem_u32(const void* p) {
    uint32_t a;
    asm("{ .reg .u64 t; cvta.to.shared.u64 t, %1; cvt.u32.u64 %0, t; }" : "=r"(a) : "l"(p));
    return a;
}
__device__ __forceinline__ float tanh_fast(float x) {
    float y; asm("tanh.approx.f32 %0, %1;" : "=f"(y) : "f"(x)); return y;
}
__device__ __forceinline__ void cp16(uint32_t s, const void* g) {
    asm volatile("cp.async.cg.shared.global [%0], [%1], 16;" :: "r"(s), "l"(g) : "memory");
}
__device__ __forceinline__ void cp_commit() {
    asm volatile("cp.async.commit_group;" ::: "memory");
}
__device__ __forceinline__ void ldsm4(uint32_t* r, uint32_t a) {
    asm volatile("ldmatrix.sync.aligned.m8n8.x4.shared.b16 {%0,%1,%2,%3}, [%4];"
                 : "=r"(r[0]), "=r"(r[1]), "=r"(r[2]), "=r"(r[3]) : "r"(a));
}
__device__ __forceinline__ void mma16816(float* c, const uint32_t* a, const uint32_t* b) {
    asm volatile("mma.sync.aligned.m16n8k16.row.col.f32.bf16.bf16.f32 "
                 "{%0,%1,%2,%3}, {%4,%5,%6,%7}, {%8,%9}, {%0,%1,%2,%3};"
                 : "+f"(c[0]), "+f"(c[1]), "+f"(c[2]), "+f"(c[3])
                 : "r"(a[0]), "r"(a[1]), "r"(a[2]), "r"(a[3]), "r"(b[0]), "r"(b[1]));
}
__device__ __forceinline__ __nv_bfloat162 pack_bf2(float a, float b) {
    return __halves2bfloat162(__float2bfloat16_rn(a), __float2bfloat16_rn(b));
}

#define ZERO_ACC(acc)                                                           \
    _Pragma("unroll") for (int _i = 0; _i < 4; _i++)                            \
    _Pragma("unroll") for (int _j = 0; _j < 4; _j++)                            \
    _Pragma("unroll") for (int _d = 0; _d < 4; _d++) (acc)[_i][_j][_d] = 0.f;

// consume one k32 chunk: A 64 rows from (abase, apitch), B warp slice (bbase, 80B rows)
__device__ __forceinline__ void consume_k32(
    uint32_t abase, int apitch, uint32_t bbase,
    float (&acc)[4][4][4], int lane)
{
    #pragma unroll
    for (int kt = 0; kt < 2; kt++) {
        uint32_t a[4][4], b[2][4];
        #pragma unroll
        for (int mt = 0; mt < 4; mt++)
            ldsm4(a[mt], abase + (mt * 16 + (lane & 15)) * apitch
                          + ((lane >> 4) << 4) + kt * 32);
        #pragma unroll
        for (int p = 0; p < 2; p++)
            ldsm4(b[p], bbase + (p * 16 + ((lane >> 4) << 3) + (lane & 7)) * 80
                         + (((lane >> 3) & 1) << 4) + kt * 32);
        #pragma unroll
        for (int mt = 0; mt < 4; mt++)
            #pragma unroll
            for (int p = 0; p < 2; p++) {
                mma16816(acc[mt][2 * p],     a[mt], &b[p][0]);
                mma16816(acc[mt][2 * p + 1], a[mt], &b[p][2]);
            }
    }
}

// fill warp-private B slot: 32 weight rows x one k32 chunk (128 16B units, 4/lane)
__device__ __forceinline__ void fillB_warp(uint32_t stg, const __nv_bfloat16* __restrict__ W,
                                           int stride, int n0w, int c, int lane)
{
    #pragma unroll
    for (int r = 0; r < 4; r++) {
        const int u = r * 32 + lane;
        const int row = u >> 2, ch = u & 3;
        cp16(stg + row * 80 + ch * 16, W + (size_t)(n0w + row) * stride + c * 32 + ch * 8);
    }
}

// ---------------------------------------------------------------------------
// Stage 1: acc = zp_tile[64 x 1024] @ W1t^T.
// B: warp-private (W1t n-slice) double buffer.  A: zpb in a 6-slot ring in the
// Y overlay, prefetch distance 4, ONE __syncthreads per k32 chunk (data lands
// ~4 chunk-periods before its barrier). Uniform 2 commits/iter -> wait_group 2.
// ---------------------------------------------------------------------------
__device__ __forceinline__ void stage1_gemm(
    uint32_t sb, const __nv_bfloat16* __restrict__ Agm,
    float (&acc)[4][4][4], int tid)
{
    const int lane = tid & 31, wn = tid >> 5;
    const uint32_t wb = sb + WB_OFF + wn * 2 * WBUF;
    ZERO_ACC(acc);

    auto fillA = [&](int s, int c) {
        // 64 rows x 4 x 16B = 256 units, 1/thread
        const int row = tid >> 2, ch = tid & 3;
        cp16(sb + Y_OFF + s * ASLOT + row * 80 + ch * 16,
             Agm + (size_t)row * ZPD + c * 32 + ch * 8);
    };

    // prologue: A chunks 0..3 in one group; B chunk 0 in one group
    fillA(0, 0); fillA(1, 1); fillA(2, 2); fillA(3, 3);
    cp_commit();
    fillB_warp(wb, g_W1t, ZPD, wn * 32, 0, lane);
    cp_commit();

    #pragma unroll 1
    for (int c = 0; c < 32; c++) {
        if (c + 4 < 32) fillA((c + 4) % 6, c + 4);
        cp_commit();
        if (c + 1 < 32) fillB_warp(wb + ((c + 1) & 1) * WBUF, g_W1t, ZPD, wn * 32, c + 1, lane);
        cp_commit();
        asm volatile("cp.async.wait_group 2;" ::: "memory");
        __syncthreads();
        consume_k32(sb + Y_OFF + (c % 6) * ASLOT, 80, wb + (c & 1) * WBUF, acc, lane);
    }
}

// ---------------------------------------------------------------------------
// Stages 2-4: A resident in smem (XPITCH rows), B warp-local double buffer.
// NO CTA barriers.
// ---------------------------------------------------------------------------
__device__ __forceinline__ void gemm_res(
    uint32_t sb, uint32_t aOff, const __nv_bfloat16* __restrict__ W,
    float (&acc)[4][4][4], int lane, int wn)
{
    ZERO_ACC(acc);
    const uint32_t wb = sb + WB_OFF + wn * 2 * WBUF;
    const int n0w = wn * 32;

    fillB_warp(wb, W, HID, n0w, 0, lane);
    cp_commit();
    #pragma unroll 1
    for (int c = 0; c < 8; c++) {
        if (c + 1 < 8) {
            fillB_warp(wb + ((c + 1) & 1) * WBUF, W, HID, n0w, c + 1, lane);
            cp_commit();
            asm volatile("cp.async.wait_group 1;" ::: "memory");
        } else {
            asm volatile("cp.async.wait_group 0;" ::: "memory");
        }
        __syncwarp();
        consume_k32(sb + aOff + c * 64, XPITCH, wb + (c & 1) * WBUF, acc, lane);
    }
}

#define EPI_BEGIN                                                               \
    _Pragma("unroll") for (int mt = 0; mt < 4; mt++)                            \
    _Pragma("unroll") for (int i2 = 0; i2 < 2; i2++) {                          \
        const int m = mt * 16 + i2 * 8 + (lane >> 2);                           \
        _Pragma("unroll") for (int nt = 0; nt < 4; nt++) {                      \
            const int n = wn * 32 + nt * 8 + 2 * (lane & 3);                    \
            const float v0 = acc[mt][nt][i2 * 2], v1 = acc[mt][nt][i2 * 2 + 1];
#define EPI_END }}

// ---------------------------------------------------------------------------
// Mega-kernel: one CTA owns 64 batch rows through ALL 9 gradH calls.
// ---------------------------------------------------------------------------
__global__ void __launch_bounds__(256, 2) leapfrog_all(
    const float* __restrict__ b1, const float* __restrict__ b2,
    const float* __restrict__ W3)
{
    extern __shared__ char smem[];
    const uint32_t sb = smem_u32(smem);
    const int tid = threadIdx.x, lane = tid & 31, wn = tid >> 5;
    const int m0 = blockIdx.x * BM;

    float acc[4][4][4];

    #pragma unroll 1
    for (int it = 0; it < 9; it++) {
        const int call = it - (it / 3) * 3;
        const int qpOff   = (call == 1) ? DIMQ : 0;
        const int colBase = (call == 1) ? 0 : DIMQ;
        const float coef  = (call == 1) ? DTC : -0.5f * DTC;

        // Stage 1: h1 = tanh(zp @ W1 + b1) -> X
        stage1_gemm(sb, g_zpb + (size_t)m0 * ZPD, acc, tid);
        EPI_BEGIN
            const float t0 = tanh_fast(v0 + __ldg(b1 + n));
            const float t1 = tanh_fast(v1 + __ldg(b1 + n + 1));
            *(__nv_bfloat162*)(smem + X_OFF + m * XPITCH + n * 2) = pack_bf2(t0, t1);
        EPI_END
        __syncthreads();

        // Stage 2: d2 = (1 - tanh(h1@W2 + b2)^2) * W3 -> Y
        gemm_res(sb, X_OFF, g_W2t, acc, lane, wn);
        EPI_BEGIN
            const float t0 = tanh_fast(v0 + __ldg(b2 + n));
            const float t1 = tanh_fast(v1 + __ldg(b2 + n + 1));
            const float r0 = (1.0f - t0 * t0) * __ldg(W3 + n);
            const float r1 = (1.0f - t1 * t1) * __ldg(W3 + n + 1);
            *(__nv_bfloat162*)(smem + Y_OFF + m * XPITCH + n * 2) = pack_bf2(r0, r1);
        EPI_END
        __syncthreads();

        // Stage 3: d1 = (d2 @ W2^T) * (1 - h1^2) -> X in-place (owner rmw)
        gemm_res(sb, Y_OFF, g_W2d, acc, lane, wn);
        EPI_BEGIN
            __nv_bfloat162* xp = (__nv_bfloat162*)(smem + X_OFF + m * XPITCH + n * 2);
            const __nv_bfloat162 hh = *xp;
            const float h0 = __bfloat162float(hh.x), h1v = __bfloat162float(hh.y);
            *xp = pack_bf2(v0 * (1.0f - h0 * h0), v1 * (1.0f - h1v * h1v));
        EPI_END
        __syncthreads();

        // Stage 4: g-half = d1 @ W1[qpOff..]^T, fused leapfrog zp update
        #pragma unroll 1
        for (int pass = 0; pass < 2; pass++) {
            gemm_res(sb, X_OFF, g_W1d + (size_t)(qpOff + pass * 256) * HID, acc, lane, wn);
            EPI_BEGIN
                const size_t o = (size_t)(m0 + m) * ZPD + colBase + pass * 256 + n;
                float2 z = *(float2*)(g_zp + o);
                z.x += coef * v0;
                z.y += coef * v1;
                *(float2*)(g_zp + o) = z;
                *(__nv_bfloat162*)(g_zpb + o) = pack_bf2(z.x, z.y);
            EPI_END
        }
        __syncthreads();   // call boundary: zp/zpb visible to next stage 1
    }
}

// ---------------- small kernels ----------------
__global__ void __launch_bounds__(256) prep_weights(const float* __restrict__ W1,
                                                    const float* __restrict__ W2)
{
    const int idx = blockIdx.x * 256 + threadIdx.x;     // 0 .. 262143
    {
        const int k = idx >> 8, n = idx & 255;
        const __nv_bfloat16 v = __float2bfloat16_rn(W1[idx]);
        g_W1d[idx] = v;
        g_W1t[n * ZPD + k] = v;
    }
    if (idx < HID * HID) {
        const int k = idx >> 8, n = idx & 255;
        const __nv_bfloat16 v = __float2bfloat16_rn(W2[idx]);
        g_W2d[idx] = v;
        g_W2t[n * HID + k] = v;
    }
}

__global__ void __launch_bounds__(256) init_zp(const float* __restrict__ z)
{
    const int i = blockIdx.x * 256 + threadIdx.x;       // over BATCH*DIMQ/4
    const int m = i / (DIMQ / 4);
    const int c = (i % (DIMQ / 4)) * 4;
    const float4 zv = *(const float4*)&z[(size_t)m * DIMQ + c];
    const size_t oq = (size_t)m * ZPD + c;
    const size_t op = oq + DIMQ;
    *(float4*)&g_zp[oq] = zv;
    *(float4*)&g_zp[op] = make_float4(0.f, 0.f, 0.f, 0.f);
    __nv_bfloat162 b01 = pack_bf2(zv.x, zv.y), b23 = pack_bf2(zv.z, zv.w);
    *(uint2*)&g_zpb[oq] = make_uint2(*(uint32_t*)&b01, *(uint32_t*)&b23);
    *(uint2*)&g_zpb[op] = make_uint2(0u, 0u);
}

__global__ void __launch_bounds__(256) write_out(float* __restrict__ out)
{
    const int i = blockIdx.x * 256 + threadIdx.x;
    const int m = i / (DIMQ / 4);
    const int c = (i % (DIMQ / 4)) * 4;
    *(float4*)&out[(size_t)m * DIMQ + c] = *(const float4*)&g_zp[(size_t)m * ZPD + c];
}

// ---------------- launcher ----------------
extern "C" void kernel_launch(void* const* d_in, const int* in_sizes, int n_in,
                              void* d_out, int out_size)
{
    const float* z  = (const float*)d_in[0];
    const float* W1 = (const float*)d_in[1];
    const float* b1 = (const float*)d_in[2];
    const float* W2 = (const float*)d_in[3];
    const float* b2 = (const float*)d_in[4];
    const float* W3 = (const float*)d_in[5];
    // d_in[6] = b3: constant, no gradient contribution.
    float* out = (float*)d_out;

    cudaFuncSetAttribute(leapfrog_all, cudaFuncAttributeMaxDynamicSharedMemorySize, SMEM_SZ);

    const dim3 blk(256);
    const dim3 grid_cp((BATCH * DIMQ / 4) / 256);

    init_zp<<<grid_cp, blk>>>(z);
    prep_weights<<<ZPD * HID / 256, blk>>>(W1, W2);
    leapfrog_all<<<BATCH / BM, blk, SMEM_SZ>>>(b1, b2, W3);
    write_out<<<grid_cp, blk>>>(out);
}

// round 11
// speedup vs baseline: 1.4815x; 1.1028x over previous
#include <cuda_runtime.h>
#include <cuda_bf16.h>
#include <stdint.h>

#define BATCH 16384
#define DIMQ  512
#define ZPD   1024
#define HID   256
#define DTC   0.1f

#define BM 64
#define XPITCH 528                        // 256 bf16 = 512B + 16B pad (ldsm conflict-free)
#define X_OFF 0                           // h1, then d1 (in-place)
#define XSZ (BM * XPITCH)                 // 33792
#define Y_OFF XSZ                         // d2; stage-1 A ring overlay (6 x 5120 = 30720)
#define ASLOT 5120                        // 64 rows x 80B
#define WB_OFF (2 * XSZ)                  // 67584: per-warp B buffers
#define WBUF 2560                         // 32 rows x 80B
#define SMEM_SZ (WB_OFF + 8 * 2 * WBUF)   // 108544 -> 2 CTAs/SM

// ---------------- device globals (no allocs allowed) ----------------
__device__ float         g_zp [BATCH * ZPD];     // fp32 master [q|p]
__device__ __nv_bfloat16 g_zpb[BATCH * ZPD];     // bf16 mirror (MMA operand)
__device__ float         g_Sq [BATCH * HID];     // cache: q @ W1[:512]
__device__ float         g_Sp [BATCH * HID];     // cache: p @ W1[512:]
__device__ __nv_bfloat16 g_W1t[HID * ZPD];       // W1^T [256][1024]
__device__ __nv_bfloat16 g_W1d[ZPD * HID];       // W1   [1024][256]
__device__ __nv_bfloat16 g_W2t[HID * HID];       // W2^T
__device__ __nv_bfloat16 g_W2d[HID * HID];       // W2

// ---------------- helpers ----------------
__device__ __forceinline__ uint32_t smem_u32(const void* p) {
    uint32_t a;
    asm("{ .reg .u64 t; cvta.to.shared.u64 t, %1; cvt.u32.u64 %0, t; }" : "=r"(a) : "l"(p));
    return a;
}
__device__ __forceinline__ float tanh_fast(float x) {
    float y; asm("tanh.approx.f32 %0, %1;" : "=f"(y) : "f"(x)); return y;
}
__device__ __forceinline__ void cp16(uint32_t s, const void* g) {
    asm volatile("cp.async.cg.shared.global [%0], [%1], 16;" :: "r"(s), "l"(g) : "memory");
}
__device__ __forceinline__ void cp_commit() {
    asm volatile("cp.async.commit_group;" ::: "memory");
}
__device__ __forceinline__ void ldsm4(uint32_t* r, uint32_t a) {
    asm volatile("ldmatrix.sync.aligned.m8n8.x4.shared.b16 {%0,%1,%2,%3}, [%4];"
                 : "=r"(r[0]), "=r"(r[1]), "=r"(r[2]), "=r"(r[3]) : "r"(a));
}
__device__ __forceinline__ void mma16816(float* c, const uint32_t* a, const uint32_t* b) {
    asm volatile("mma.sync.aligned.m16n8k16.row.col.f32.bf16.bf16.f32 "
                 "{%0,%1,%2,%3}, {%4,%5,%6,%7}, {%8,%9}, {%0,%1,%2,%3};"
                 : "+f"(c[0]), "+f"(c[1]), "+f"(c[2]), "+f"(c[3])
                 : "r"(a[0]), "r"(a[1]), "r"(a[2]), "r"(a[3]), "r"(b[0]), "r"(b[1]));
}
__device__ __forceinline__ __nv_bfloat162 pack_bf2(float a, float b) {
    return __halves2bfloat162(__float2bfloat16_rn(a), __float2bfloat16_rn(b));
}

#define ZERO_ACC(acc)                                                           \
    _Pragma("unroll") for (int _i = 0; _i < 4; _i++)                            \
    _Pragma("unroll") for (int _j = 0; _j < 4; _j++)                            \
    _Pragma("unroll") for (int _d = 0; _d < 4; _d++) (acc)[_i][_j][_d] = 0.f;

// consume one k32 chunk: A 64 rows from (abase, apitch), B warp slice (bbase, 80B rows)
__device__ __forceinline__ void consume_k32(
    uint32_t abase, int apitch, uint32_t bbase,
    float (&acc)[4][4][4], int lane)
{
    #pragma unroll
    for (int kt = 0; kt < 2; kt++) {
        uint32_t a[4][4], b[2][4];
        #pragma unroll
        for (int mt = 0; mt < 4; mt++)
            ldsm4(a[mt], abase + (mt * 16 + (lane & 15)) * apitch
                          + ((lane >> 4) << 4) + kt * 32);
        #pragma unroll
        for (int p = 0; p < 2; p++)
            ldsm4(b[p], bbase + (p * 16 + ((lane >> 4) << 3) + (lane & 7)) * 80
                         + (((lane >> 3) & 1) << 4) + kt * 32);
        #pragma unroll
        for (int mt = 0; mt < 4; mt++)
            #pragma unroll
            for (int p = 0; p < 2; p++) {
                mma16816(acc[mt][2 * p],     a[mt], &b[p][0]);
                mma16816(acc[mt][2 * p + 1], a[mt], &b[p][2]);
            }
    }
}

// fill warp-private B slot: 32 weight rows x one k32 chunk (128 16B units, 4/lane)
__device__ __forceinline__ void fillB_warp(uint32_t stg, const __nv_bfloat16* __restrict__ W,
                                           int stride, int n0w, int c, int lane)
{
    #pragma unroll
    for (int r = 0; r < 4; r++) {
        const int u = r * 32 + lane;
        const int row = u >> 2, ch = u & 3;
        cp16(stg + row * 80 + ch * 16, W + (size_t)(n0w + row) * stride + c * 32 + ch * 8);
    }
}

// ---------------------------------------------------------------------------
// Stage 1 (half): acc = zp_half[64 x 512] @ W1t_half^T.  Agm/Bgm pre-offset to
// the active K-half.  B: warp-private double buffer.  A: 6-slot ring in the Y
// overlay, prefetch distance 4, ONE __syncthreads per k32 chunk.
// ---------------------------------------------------------------------------
__device__ __forceinline__ void stage1_gemm(
    uint32_t sb, const __nv_bfloat16* __restrict__ Agm,
    const __nv_bfloat16* __restrict__ Bgm,
    float (&acc)[4][4][4], int tid)
{
    const int lane = tid & 31, wn = tid >> 5;
    const uint32_t wb = sb + WB_OFF + wn * 2 * WBUF;
    ZERO_ACC(acc);

    auto fillA = [&](int s, int c) {
        // 64 rows x 4 x 16B = 256 units, 1/thread
        const int row = tid >> 2, ch = tid & 3;
        cp16(sb + Y_OFF + s * ASLOT + row * 80 + ch * 16,
             Agm + (size_t)row * ZPD + c * 32 + ch * 8);
    };

    fillA(0, 0); fillA(1, 1); fillA(2, 2); fillA(3, 3);
    cp_commit();
    fillB_warp(wb, Bgm, ZPD, wn * 32, 0, lane);
    cp_commit();

    #pragma unroll 1
    for (int c = 0; c < 16; c++) {
        if (c + 4 < 16) fillA((c + 4) % 6, c + 4);
        cp_commit();
        if (c + 1 < 16) fillB_warp(wb + ((c + 1) & 1) * WBUF, Bgm, ZPD, wn * 32, c + 1, lane);
        cp_commit();
        asm volatile("cp.async.wait_group 2;" ::: "memory");
        __syncthreads();
        consume_k32(sb + Y_OFF + (c % 6) * ASLOT, 80, wb + (c & 1) * WBUF, acc, lane);
    }
}

// ---------------------------------------------------------------------------
// Stages 2-4: A resident in smem (XPITCH rows), B warp-local double buffer.
// NO CTA barriers.
// ---------------------------------------------------------------------------
__device__ __forceinline__ void gemm_res(
    uint32_t sb, uint32_t aOff, const __nv_bfloat16* __restrict__ W,
    float (&acc)[4][4][4], int lane, int wn)
{
    ZERO_ACC(acc);
    const uint32_t wb = sb + WB_OFF + wn * 2 * WBUF;
    const int n0w = wn * 32;

    fillB_warp(wb, W, HID, n0w, 0, lane);
    cp_commit();
    #pragma unroll 1
    for (int c = 0; c < 8; c++) {
        if (c + 1 < 8) {
            fillB_warp(wb + ((c + 1) & 1) * WBUF, W, HID, n0w, c + 1, lane);
            cp_commit();
            asm volatile("cp.async.wait_group 1;" ::: "memory");
        } else {
            asm volatile("cp.async.wait_group 0;" ::: "memory");
        }
        __syncwarp();
        consume_k32(sb + aOff + c * 64, XPITCH, wb + (c & 1) * WBUF, acc, lane);
    }
}

#define EPI_BEGIN                                                               \
    _Pragma("unroll") for (int mt = 0; mt < 4; mt++)                            \
    _Pragma("unroll") for (int i2 = 0; i2 < 2; i2++) {                          \
        const int m = mt * 16 + i2 * 8 + (lane >> 2);                           \
        _Pragma("unroll") for (int nt = 0; nt < 4; nt++) {                      \
            const int n = wn * 32 + nt * 8 + 2 * (lane & 3);                    \
            const float v0 = acc[mt][nt][i2 * 2], v1 = acc[mt][nt][i2 * 2 + 1];
#define EPI_END }}

// ---------------------------------------------------------------------------
// Mega-kernel: one CTA owns 64 batch rows through ALL 9 gradH calls.
// Stage-1 half-caching: pre1 = Sq + Sp; recompute only the half whose input
// changed since the previous call (it0: Sq only, since p == 0 -> Sp == 0).
// ---------------------------------------------------------------------------
__global__ void __launch_bounds__(256, 2) leapfrog_all(
    const float* __restrict__ b1, const float* __restrict__ b2,
    const float* __restrict__ W3)
{
    extern __shared__ char smem[];
    const uint32_t sb = smem_u32(smem);
    const int tid = threadIdx.x, lane = tid & 31, wn = tid >> 5;
    const int m0 = blockIdx.x * BM;

    float acc[4][4][4];

    #pragma unroll 1
    for (int it = 0; it < 9; it++) {
        const int call = it - (it / 3) * 3;
        const int qpOff   = (call == 1) ? DIMQ : 0;
        const int colBase = (call == 1) ? 0 : DIMQ;
        const float coef  = (call == 1) ? DTC : -0.5f * DTC;

        // which half to recompute: prev call1 updated q -> Sq; prev call0/2 -> Sp.
        // it==0: Sq (and Sp == 0 identically).
        const int rec = (it == 0) ? 0 : ((call == 2) ? 0 : 1);   // 0 = q-half, 1 = p-half
        const int cOff = rec ? DIMQ : 0;

        // Stage 1 (half K): fresh = zp_half @ W1_half
        stage1_gemm(sb, g_zpb + (size_t)m0 * ZPD + cOff, g_W1t + cOff, acc, tid);
        {
            float* recS = rec ? g_Sp : g_Sq;
            const float* othS = rec ? g_Sq : g_Sp;      // it==0: unused (Sp==0)
            const bool useOth = (it != 0);
            EPI_BEGIN
                const size_t o = (size_t)(m0 + m) * HID + n;
                *(float2*)(recS + o) = make_float2(v0, v1);
                float c0 = 0.f, c1 = 0.f;
                if (useOth) { const float2 cc = *(const float2*)(othS + o); c0 = cc.x; c1 = cc.y; }
                const float t0 = tanh_fast(v0 + c0 + __ldg(b1 + n));
                const float t1 = tanh_fast(v1 + c1 + __ldg(b1 + n + 1));
                *(__nv_bfloat162*)(smem + X_OFF + m * XPITCH + n * 2) = pack_bf2(t0, t1);
            EPI_END
        }
        __syncthreads();

        // Stage 2: d2 = (1 - tanh(h1@W2 + b2)^2) * W3 -> Y
        gemm_res(sb, X_OFF, g_W2t, acc, lane, wn);
        EPI_BEGIN
            const float t0 = tanh_fast(v0 + __ldg(b2 + n));
            const float t1 = tanh_fast(v1 + __ldg(b2 + n + 1));
            const float r0 = (1.0f - t0 * t0) * __ldg(W3 + n);
            const float r1 = (1.0f - t1 * t1) * __ldg(W3 + n + 1);
            *(__nv_bfloat162*)(smem + Y_OFF + m * XPITCH + n * 2) = pack_bf2(r0, r1);
        EPI_END
        __syncthreads();

        // Stage 3: d1 = (d2 @ W2^T) * (1 - h1^2) -> X in-place (owner rmw)
        gemm_res(sb, Y_OFF, g_W2d, acc, lane, wn);
        EPI_BEGIN
            __nv_bfloat162* xp = (__nv_bfloat162*)(smem + X_OFF + m * XPITCH + n * 2);
            const __nv_bfloat162 hh = *xp;
            const float h0 = __bfloat162float(hh.x), h1v = __bfloat162float(hh.y);
            *xp = pack_bf2(v0 * (1.0f - h0 * h0), v1 * (1.0f - h1v * h1v));
        EPI_END
        __syncthreads();

        // Stage 4: g-half = d1 @ W1[qpOff..]^T, fused leapfrog zp update
        #pragma unroll 1
        for (int pass = 0; pass < 2; pass++) {
            gemm_res(sb, X_OFF, g_W1d + (size_t)(qpOff + pass * 256) * HID, acc, lane, wn);
            EPI_BEGIN
                const size_t o = (size_t)(m0 + m) * ZPD + colBase + pass * 256 + n;
                float2 z = *(float2*)(g_zp + o);
                z.x += coef * v0;
                z.y += coef * v1;
                *(float2*)(g_zp + o) = z;
                *(__nv_bfloat162*)(g_zpb + o) = pack_bf2(z.x, z.y);
            EPI_END
        }
        __syncthreads();   // call boundary: zp/zpb visible to next stage 1
    }
}

// ---------------- small kernels ----------------
__global__ void __launch_bounds__(256) prep_weights(const float* __restrict__ W1,
                                                    const float* __restrict__ W2)
{
    const int idx = blockIdx.x * 256 + threadIdx.x;     // 0 .. 262143
    {
        const int k = idx >> 8, n = idx & 255;
        const __nv_bfloat16 v = __float2bfloat16_rn(W1[idx]);
        g_W1d[idx] = v;
        g_W1t[n * ZPD + k] = v;
    }
    if (idx < HID * HID) {
        const int k = idx >> 8, n = idx & 255;
        const __nv_bfloat16 v = __float2bfloat16_rn(W2[idx]);
        g_W2d[idx] = v;
        g_W2t[n * HID + k] = v;
    }
}

__global__ void __launch_bounds__(256) init_zp(const float* __restrict__ z)
{
    const int i = blockIdx.x * 256 + threadIdx.x;       // over BATCH*DIMQ/4
    const int m = i / (DIMQ / 4);
    const int c = (i % (DIMQ / 4)) * 4;
    const float4 zv = *(const float4*)&z[(size_t)m * DIMQ + c];
    const size_t oq = (size_t)m * ZPD + c;
    const size_t op = oq + DIMQ;
    *(float4*)&g_zp[oq] = zv;
    *(float4*)&g_zp[op] = make_float4(0.f, 0.f, 0.f, 0.f);
    __nv_bfloat162 b01 = pack_bf2(zv.x, zv.y), b23 = pack_bf2(zv.z, zv.w);
    *(uint2*)&g_zpb[oq] = make_uint2(*(uint32_t*)&b01, *(uint32_t*)&b23);
    *(uint2*)&g_zpb[op] = make_uint2(0u, 0u);
}

__global__ void __launch_bounds__(256) write_out(float* __restrict__ out)
{
    const int i = blockIdx.x * 256 + threadIdx.x;
    const int m = i / (DIMQ / 4);
    const int c = (i % (DIMQ / 4)) * 4;
    *(float4*)&out[(size_t)m * DIMQ + c] = *(const float4*)&g_zp[(size_t)m * ZPD + c];
}

// ---------------- launcher ----------------
extern "C" void kernel_launch(void* const* d_in, const int* in_sizes, int n_in,
                              void* d_out, int out_size)
{
    const float* z  = (const float*)d_in[0];
    const float* W1 = (const float*)d_in[1];
    const float* b1 = (const float*)d_in[2];
    const float* W2 = (const float*)d_in[3];
    const float* b2 = (const float*)d_in[4];
    const float* W3 = (const float*)d_in[5];
    // d_in[6] = b3: constant, no gradient contribution.
    float* out = (float*)d_out;

    cudaFuncSetAttribute(leapfrog_all, cudaFuncAttributeMaxDynamicSharedMemorySize, SMEM_SZ);

    const dim3 blk(256);
    const dim3 grid_cp((BATCH * DIMQ / 4) / 256);

    init_zp<<<grid_cp, blk>>>(z);
    prep_weights<<<ZPD * HID / 256, blk>>>(W1, W2);
    leapfrog_all<<<BATCH / BM, blk, SMEM_SZ>>>(b1, b2, W3);
    write_out<<<grid_cp, blk>>>(out);
}

// round 12
// speedup vs baseline: 1.5515x; 1.0472x over previous
#include <cuda_runtime.h>
#include <cuda_bf16.h>
#include <stdint.h>

#define BATCH 16384
#define DIMQ  512
#define ZPD   1024
#define HID   256
#define DTC   0.1f

// grid: 136 CTAs x 64 rows + 160 CTAs x 48 rows = 296 CTAs = 2 x 148 SMs
#define N64CTAS 136
#define NGRID   296

#define XPITCH 528                        // 256 bf16 = 512B + 16B pad (ldsm conflict-free)
#define X_OFF 0                           // h1, then d1 (in-place)
#define XSZ (64 * XPITCH)                 // 33792 (sized for max 64 rows)
#define Y_OFF XSZ                         // d2; stage-1 A ring overlay (6 x 5120 = 30720)
#define ASLOT 5120                        // 64 rows x 80B
#define WB_OFF (2 * XSZ)                  // 67584: per-warp B buffers
#define WBUF 2560                         // 32 rows x 80B
#define SMEM_SZ (WB_OFF + 8 * 2 * WBUF)   // 108544 -> 2 CTAs/SM

// ---------------- device globals (no allocs allowed) ----------------
__device__ float         g_zp [BATCH * ZPD];     // fp32 master [q|p]
__device__ __nv_bfloat16 g_zpb[BATCH * ZPD];     // bf16 mirror (MMA operand)
__device__ float         g_Sq [BATCH * HID];     // cache: q @ W1[:512]
__device__ float         g_Sp [BATCH * HID];     // cache: p @ W1[512:]
__device__ __nv_bfloat16 g_W1t[HID * ZPD];       // W1^T [256][1024]
__device__ __nv_bfloat16 g_W1d[ZPD * HID];       // W1   [1024][256]
__device__ __nv_bfloat16 g_W2t[HID * HID];       // W2^T
__device__ __nv_bfloat16 g_W2d[HID * HID];       // W2

// ---------------- helpers ----------------
__device__ __forceinline__ uint32_t smem_u32(const void* p) {
    uint32_t a;
    asm("{ .reg .u64 t; cvta.to.shared.u64 t, %1; cvt.u32.u64 %0, t; }" : "=r"(a) : "l"(p));
    return a;
}
__device__ __forceinline__ float tanh_fast(float x) {
    float y; asm("tanh.approx.f32 %0, %1;" : "=f"(y) : "f"(x)); return y;
}
__device__ __forceinline__ void cp16(uint32_t s, const void* g) {
    asm volatile("cp.async.cg.shared.global [%0], [%1], 16;" :: "r"(s), "l"(g) : "memory");
}
__device__ __forceinline__ void cp_commit() {
    asm volatile("cp.async.commit_group;" ::: "memory");
}
__device__ __forceinline__ void ldsm4(uint32_t* r, uint32_t a) {
    asm volatile("ldmatrix.sync.aligned.m8n8.x4.shared.b16 {%0,%1,%2,%3}, [%4];"
                 : "=r"(r[0]), "=r"(r[1]), "=r"(r[2]), "=r"(r[3]) : "r"(a));
}
__device__ __forceinline__ void mma16816(float* c, const uint32_t* a, const uint32_t* b) {
    asm volatile("mma.sync.aligned.m16n8k16.row.col.f32.bf16.bf16.f32 "
                 "{%0,%1,%2,%3}, {%4,%5,%6,%7}, {%8,%9}, {%0,%1,%2,%3};"
                 : "+f"(c[0]), "+f"(c[1]), "+f"(c[2]), "+f"(c[3])
                 : "r"(a[0]), "r"(a[1]), "r"(a[2]), "r"(a[3]), "r"(b[0]), "r"(b[1]));
}
__device__ __forceinline__ __nv_bfloat162 pack_bf2(float a, float b) {
    return __halves2bfloat162(__float2bfloat16_rn(a), __float2bfloat16_rn(b));
}

#define ZERO_ACC(acc, NMT)                                                      \
    _Pragma("unroll") for (int _i = 0; _i < NMT; _i++)                          \
    _Pragma("unroll") for (int _j = 0; _j < 4; _j++)                            \
    _Pragma("unroll") for (int _d = 0; _d < 4; _d++) (acc)[_i][_j][_d] = 0.f;

// consume one k32 chunk: A NMT*16 rows from (abase, apitch), B warp slice (80B rows)
template <int NMT>
__device__ __forceinline__ void consume_k32(
    uint32_t abase, int apitch, uint32_t bbase,
    float (&acc)[4][4][4], int lane)
{
    #pragma unroll
    for (int kt = 0; kt < 2; kt++) {
        uint32_t a[NMT][4], b[2][4];
        #pragma unroll
        for (int mt = 0; mt < NMT; mt++)
            ldsm4(a[mt], abase + (mt * 16 + (lane & 15)) * apitch
                          + ((lane >> 4) << 4) + kt * 32);
        #pragma unroll
        for (int p = 0; p < 2; p++)
            ldsm4(b[p], bbase + (p * 16 + ((lane >> 4) << 3) + (lane & 7)) * 80
                         + (((lane >> 3) & 1) << 4) + kt * 32);
        #pragma unroll
        for (int mt = 0; mt < NMT; mt++)
            #pragma unroll
            for (int p = 0; p < 2; p++) {
                mma16816(acc[mt][2 * p],     a[mt], &b[p][0]);
                mma16816(acc[mt][2 * p + 1], a[mt], &b[p][2]);
            }
    }
}

// fill warp-private B slot: 32 weight rows x one k32 chunk (128 16B units, 4/lane)
__device__ __forceinline__ void fillB_warp(uint32_t stg, const __nv_bfloat16* __restrict__ W,
                                           int stride, int n0w, int c, int lane)
{
    #pragma unroll
    for (int r = 0; r < 4; r++) {
        const int u = r * 32 + lane;
        const int row = u >> 2, ch = u & 3;
        cp16(stg + row * 80 + ch * 16, W + (size_t)(n0w + row) * stride + c * 32 + ch * 8);
    }
}

// ---------------------------------------------------------------------------
// Stage 1 (half K): acc = zp_half[M x 512] @ W1t_half^T.  B: warp-private
// double buffer. A: 6-slot ring in Y overlay, prefetch distance 4, one
// __syncthreads per k32 chunk.
// ---------------------------------------------------------------------------
template <int NMT>
__device__ __forceinline__ void stage1_gemm(
    uint32_t sb, const __nv_bfloat16* __restrict__ Agm,
    const __nv_bfloat16* __restrict__ Bgm,
    float (&acc)[4][4][4], int tid)
{
    const int lane = tid & 31, wn = tid >> 5;
    const uint32_t wb = sb + WB_OFF + wn * 2 * WBUF;
    ZERO_ACC(acc, NMT);

    auto fillA = [&](int s, int c) {
        if (tid < NMT * 64) {   // NMT*16 rows x 4 x 16B units, 1/thread
            const int row = tid >> 2, ch = tid & 3;
            cp16(sb + Y_OFF + s * ASLOT + row * 80 + ch * 16,
                 Agm + (size_t)row * ZPD + c * 32 + ch * 8);
        }
    };

    fillA(0, 0); fillA(1, 1); fillA(2, 2); fillA(3, 3);
    cp_commit();
    fillB_warp(wb, Bgm, ZPD, wn * 32, 0, lane);
    cp_commit();

    #pragma unroll 1
    for (int c = 0; c < 16; c++) {
        if (c + 4 < 16) fillA((c + 4) % 6, c + 4);
        cp_commit();
        if (c + 1 < 16) fillB_warp(wb + ((c + 1) & 1) * WBUF, Bgm, ZPD, wn * 32, c + 1, lane);
        cp_commit();
        asm volatile("cp.async.wait_group 2;" ::: "memory");
        __syncthreads();
        consume_k32<NMT>(sb + Y_OFF + (c % 6) * ASLOT, 80, wb + (c & 1) * WBUF, acc, lane);
    }
}

// ---------------------------------------------------------------------------
// Stages 2-4: A resident in smem (XPITCH rows), B warp-local double buffer.
// NO CTA barriers.
// ---------------------------------------------------------------------------
template <int NMT>
__device__ __forceinline__ void gemm_res(
    uint32_t sb, uint32_t aOff, const __nv_bfloat16* __restrict__ W,
    float (&acc)[4][4][4], int lane, int wn)
{
    ZERO_ACC(acc, NMT);
    const uint32_t wb = sb + WB_OFF + wn * 2 * WBUF;
    const int n0w = wn * 32;

    fillB_warp(wb, W, HID, n0w, 0, lane);
    cp_commit();
    #pragma unroll 1
    for (int c = 0; c < 8; c++) {
        if (c + 1 < 8) {
            fillB_warp(wb + ((c + 1) & 1) * WBUF, W, HID, n0w, c + 1, lane);
            cp_commit();
            asm volatile("cp.async.wait_group 1;" ::: "memory");
        } else {
            asm volatile("cp.async.wait_group 0;" ::: "memory");
        }
        __syncwarp();
        consume_k32<NMT>(sb + aOff + c * 64, XPITCH, wb + (c & 1) * WBUF, acc, lane);
    }
}

#define EPI_BEGIN(NMT)                                                          \
    _Pragma("unroll") for (int mt = 0; mt < NMT; mt++)                          \
    _Pragma("unroll") for (int i2 = 0; i2 < 2; i2++) {                          \
        const int m = mt * 16 + i2 * 8 + (lane >> 2);                           \
        _Pragma("unroll") for (int nt = 0; nt < 4; nt++) {                      \
            const int n = wn * 32 + nt * 8 + 2 * (lane & 3);                    \
            const float v0 = acc[mt][nt][i2 * 2], v1 = acc[mt][nt][i2 * 2 + 1];
#define EPI_END }}

// ---------------------------------------------------------------------------
// Leapfrog body: one CTA owns NMT*16 batch rows through all 9 gradH calls.
// Stage-1 half-caching: pre1 = Sq + Sp; recompute only the changed half.
// ---------------------------------------------------------------------------
template <int NMT>
__device__ __forceinline__ void leapfrog_body(
    uint32_t sb, char* smem, int m0,
    const float* __restrict__ b1, const float* __restrict__ b2,
    const float* __restrict__ W3)
{
    const int tid = threadIdx.x, lane = tid & 31, wn = tid >> 5;
    float acc[4][4][4];

    #pragma unroll 1
    for (int it = 0; it < 9; it++) {
        const int call = it - (it / 3) * 3;
        const int qpOff   = (call == 1) ? DIMQ : 0;
        const int colBase = (call == 1) ? 0 : DIMQ;
        const float coef  = (call == 1) ? DTC : -0.5f * DTC;
        const int rec = (it == 0) ? 0 : ((call == 2) ? 0 : 1);   // 0 = q-half, 1 = p-half
        const int cOff = rec ? DIMQ : 0;

        // Stage 1 (half K): fresh = zp_half @ W1_half
        stage1_gemm<NMT>(sb, g_zpb + (size_t)m0 * ZPD + cOff, g_W1t + cOff, acc, tid);
        {
            float* recS = rec ? g_Sp : g_Sq;
            const float* othS = rec ? g_Sq : g_Sp;      // it==0: unused (Sp==0)
            const bool useOth = (it != 0);
            EPI_BEGIN(NMT)
                const size_t o = (size_t)(m0 + m) * HID + n;
                *(float2*)(recS + o) = make_float2(v0, v1);
                float c0 = 0.f, c1 = 0.f;
                if (useOth) { const float2 cc = *(const float2*)(othS + o); c0 = cc.x; c1 = cc.y; }
                const float t0 = tanh_fast(v0 + c0 + __ldg(b1 + n));
                const float t1 = tanh_fast(v1 + c1 + __ldg(b1 + n + 1));
                *(__nv_bfloat162*)(smem + X_OFF + m * XPITCH + n * 2) = pack_bf2(t0, t1);
            EPI_END
        }
        __syncthreads();

        // Stage 2: d2 = (1 - tanh(h1@W2 + b2)^2) * W3 -> Y
        gemm_res<NMT>(sb, X_OFF, g_W2t, acc, lane, wn);
        EPI_BEGIN(NMT)
            const float t0 = tanh_fast(v0 + __ldg(b2 + n));
            const float t1 = tanh_fast(v1 + __ldg(b2 + n + 1));
            const float r0 = (1.0f - t0 * t0) * __ldg(W3 + n);
            const float r1 = (1.0f - t1 * t1) * __ldg(W3 + n + 1);
            *(__nv_bfloat162*)(smem + Y_OFF + m * XPITCH + n * 2) = pack_bf2(r0, r1);
        EPI_END
        __syncthreads();

        // Stage 3: d1 = (d2 @ W2^T) * (1 - h1^2) -> X in-place (owner rmw)
        gemm_res<NMT>(sb, Y_OFF, g_W2d, acc, lane, wn);
        EPI_BEGIN(NMT)
            __nv_bfloat162* xp = (__nv_bfloat162*)(smem + X_OFF + m * XPITCH + n * 2);
            const __nv_bfloat162 hh = *xp;
            const float h0 = __bfloat162float(hh.x), h1v = __bfloat162float(hh.y);
            *xp = pack_bf2(v0 * (1.0f - h0 * h0), v1 * (1.0f - h1v * h1v));
        EPI_END
        __syncthreads();

        // Stage 4: g-half = d1 @ W1[qpOff..]^T, fused leapfrog zp update
        #pragma unroll 1
        for (int pass = 0; pass < 2; pass++) {
            gemm_res<NMT>(sb, X_OFF, g_W1d + (size_t)(qpOff + pass * 256) * HID, acc, lane, wn);
            EPI_BEGIN(NMT)
                const size_t o = (size_t)(m0 + m) * ZPD + colBase + pass * 256 + n;
                float2 z = *(float2*)(g_zp + o);
                z.x += coef * v0;
                z.y += coef * v1;
                *(float2*)(g_zp + o) = z;
                *(__nv_bfloat162*)(g_zpb + o) = pack_bf2(z.x, z.y);
            EPI_END
        }
        __syncthreads();   // call boundary: zp/zpb visible to next stage 1
    }
}

__global__ void __launch_bounds__(256, 2) leapfrog_all(
    const float* __restrict__ b1, const float* __restrict__ b2,
    const float* __restrict__ W3)
{
    extern __shared__ char smem[];
    const uint32_t sb = smem_u32(smem);
    const int bx = blockIdx.x;
    if (bx < N64CTAS) {
        leapfrog_body<4>(sb, smem, bx * 64, b1, b2, W3);
    } else {
        leapfrog_body<3>(sb, smem, N64CTAS * 64 + (bx - N64CTAS) * 48, b1, b2, W3);
    }
}

// ---------------- small kernels ----------------
__global__ void __launch_bounds__(256) prep_weights(const float* __restrict__ W1,
                                                    const float* __restrict__ W2)
{
    const int idx = blockIdx.x * 256 + threadIdx.x;     // 0 .. 262143
    {
        const int k = idx >> 8, n = idx & 255;
        const __nv_bfloat16 v = __float2bfloat16_rn(W1[idx]);
        g_W1d[idx] = v;
        g_W1t[n * ZPD + k] = v;
    }
    if (idx < HID * HID) {
        const int k = idx >> 8, n = idx & 255;
        const __nv_bfloat16 v = __float2bfloat16_rn(W2[idx]);
        g_W2d[idx] = v;
        g_W2t[n * HID + k] = v;
    }
}

__global__ void __launch_bounds__(256) init_zp(const float* __restrict__ z)
{
    const int i = blockIdx.x * 256 + threadIdx.x;       // over BATCH*DIMQ/4
    const int m = i / (DIMQ / 4);
    const int c = (i % (DIMQ / 4)) * 4;
    const float4 zv = *(const float4*)&z[(size_t)m * DIMQ + c];
    const size_t oq = (size_t)m * ZPD + c;
    const size_t op = oq + DIMQ;
    *(float4*)&g_zp[oq] = zv;
    *(float4*)&g_zp[op] = make_float4(0.f, 0.f, 0.f, 0.f);
    __nv_bfloat162 b01 = pack_bf2(zv.x, zv.y), b23 = pack_bf2(zv.z, zv.w);
    *(uint2*)&g_zpb[oq] = make_uint2(*(uint32_t*)&b01, *(uint32_t*)&b23);
    *(uint2*)&g_zpb[op] = make_uint2(0u, 0u);
}

__global__ void __launch_bounds__(256) write_out(float* __restrict__ out)
{
    const int i = blockIdx.x * 256 + threadIdx.x;
    const int m = i / (DIMQ / 4);
    const int c = (i % (DIMQ / 4)) * 4;
    *(float4*)&out[(size_t)m * DIMQ + c] = *(const float4*)&g_zp[(size_t)m * ZPD + c];
}

// ---------------- launcher ----------------
extern "C" void kernel_launch(void* const* d_in, const int* in_sizes, int n_in,
                              void* d_out, int out_size)
{
    const float* z  = (const float*)d_in[0];
    const float* W1 = (const float*)d_in[1];
    const float* b1 = (const float*)d_in[2];
    const float* W2 = (const float*)d_in[3];
    const float* b2 = (const float*)d_in[4];
    const float* W3 = (const float*)d_in[5];
    // d_in[6] = b3: constant, no gradient contribution.
    float* out = (float*)d_out;

    cudaFuncSetAttribute(leapfrog_all, cudaFuncAttributeMaxDynamicSharedMemorySize, SMEM_SZ);

    const dim3 blk(256);
    const dim3 grid_cp((BATCH * DIMQ / 4) / 256);

    init_zp<<<grid_cp, blk>>>(z);
    prep_weights<<<ZPD * HID / 256, blk>>>(W1, W2);
    leapfrog_all<<<NGRID, blk, SMEM_SZ>>>(b1, b2, W3);
    write_out<<<grid_cp, blk>>>(out);
}

// round 13
// speedup vs baseline: 1.7412x; 1.1223x over previous
#include <cuda_runtime.h>
#include <cuda_bf16.h>
#include <stdint.h>

#define BATCH 16384
#define DIMQ  512
#define ZPD   1024
#define HID   256
#define DTC   0.1f

// grid: 136 CTAs x 64 rows + 160 CTAs x 48 rows = 296 CTAs = 2 x 148 SMs
#define N64CTAS 136
#define NGRID   296

#define XPITCH 528                        // 256 bf16 = 512B + 16B pad (ldsm conflict-free)
#define X_OFF 0                           // h1, then d1 (in-place)
#define XSZ (64 * XPITCH)                 // 33792 (sized for max 64 rows)
#define Y_OFF XSZ                         // d2; stage-1 A ring overlay (6 x 5120 = 30720)
#define ASLOT 5120                        // 64 rows x 80B
#define WB_OFF (2 * XSZ)                  // 67584: per-warp B buffers
#define WBUF 2560                         // 32 rows x 80B
#define SMEM_SZ (WB_OFF + 8 * 2 * WBUF)   // 108544 -> 2 CTAs/SM

// ---------------- device globals (no allocs allowed) ----------------
__device__ float         g_zp [BATCH * ZPD];     // fp32 master [q|p]
__device__ __nv_bfloat16 g_zpb[BATCH * ZPD];     // bf16 mirror (MMA operand)
__device__ float         g_Sq [BATCH * HID];     // cache: q @ W1[:512]
__device__ float         g_Sp [BATCH * HID];     // cache: p @ W1[512:]
__device__ __nv_bfloat16 g_W1t[HID * ZPD];       // W1^T [256][1024]
__device__ __nv_bfloat16 g_W1d[ZPD * HID];       // W1   [1024][256]
__device__ __nv_bfloat16 g_W2t[HID * HID];       // W2^T
__device__ __nv_bfloat16 g_W2d[HID * HID];       // W2

// ---------------- helpers ----------------
__device__ __forceinline__ uint32_t smem_u32(const void* p) {
    uint32_t a;
    asm("{ .reg .u64 t; cvta.to.shared.u64 t, %1; cvt.u32.u64 %0, t; }" : "=r"(a) : "l"(p));
    return a;
}
__device__ __forceinline__ float tanh_fast(float x) {
    float y; asm("tanh.approx.f32 %0, %1;" : "=f"(y) : "f"(x)); return y;
}
__device__ __forceinline__ void cp16(uint32_t s, const void* g) {
    asm volatile("cp.async.cg.shared.global [%0], [%1], 16;" :: "r"(s), "l"(g) : "memory");
}
__device__ __forceinline__ void cp_commit() {
    asm volatile("cp.async.commit_group;" ::: "memory");
}
__device__ __forceinline__ void ldsm4(uint32_t* r, uint32_t a) {
    asm volatile("ldmatrix.sync.aligned.m8n8.x4.shared.b16 {%0,%1,%2,%3}, [%4];"
                 : "=r"(r[0]), "=r"(r[1]), "=r"(r[2]), "=r"(r[3]) : "r"(a));
}
__device__ __forceinline__ void mma16816(float* c, const uint32_t* a, const uint32_t* b) {
    asm volatile("mma.sync.aligned.m16n8k16.row.col.f32.bf16.bf16.f32 "
                 "{%0,%1,%2,%3}, {%4,%5,%6,%7}, {%8,%9}, {%0,%1,%2,%3};"
                 : "+f"(c[0]), "+f"(c[1]), "+f"(c[2]), "+f"(c[3])
                 : "r"(a[0]), "r"(a[1]), "r"(a[2]), "r"(a[3]), "r"(b[0]), "r"(b[1]));
}
__device__ __forceinline__ __nv_bfloat162 pack_bf2(float a, float b) {
    return __halves2bfloat162(__float2bfloat16_rn(a), __float2bfloat16_rn(b));
}

#define ZERO_ACC(acc, NMT)                                                      \
    _Pragma("unroll") for (int _i = 0; _i < NMT; _i++)                          \
    _Pragma("unroll") for (int _j = 0; _j < 4; _j++)                            \
    _Pragma("unroll") for (int _d = 0; _d < 4; _d++) (acc)[_i][_j][_d] = 0.f;

// consume one k32 chunk: A NMT*16 rows from (abase, apitch), B warp slice (80B rows)
template <int NMT>
__device__ __forceinline__ void consume_k32(
    uint32_t abase, int apitch, uint32_t bbase,
    float (&acc)[4][4][4], int lane)
{
    #pragma unroll
    for (int kt = 0; kt < 2; kt++) {
        uint32_t a[NMT][4], b[2][4];
        #pragma unroll
        for (int mt = 0; mt < NMT; mt++)
            ldsm4(a[mt], abase + (mt * 16 + (lane & 15)) * apitch
                          + ((lane >> 4) << 4) + kt * 32);
        #pragma unroll
        for (int p = 0; p < 2; p++)
            ldsm4(b[p], bbase + (p * 16 + ((lane >> 4) << 3) + (lane & 7)) * 80
                         + (((lane >> 3) & 1) << 4) + kt * 32);
        #pragma unroll
        for (int mt = 0; mt < NMT; mt++)
            #pragma unroll
            for (int p = 0; p < 2; p++) {
                mma16816(acc[mt][2 * p],     a[mt], &b[p][0]);
                mma16816(acc[mt][2 * p + 1], a[mt], &b[p][2]);
            }
    }
}

// fill warp-private B slot: 32 weight rows x one k32 chunk (128 16B units, 4/lane)
__device__ __forceinline__ void fillB_warp(uint32_t stg, const __nv_bfloat16* __restrict__ W,
                                           int stride, int n0w, int c, int lane)
{
    #pragma unroll
    for (int r = 0; r < 4; r++) {
        const int u = r * 32 + lane;
        const int row = u >> 2, ch = u & 3;
        cp16(stg + row * 80 + ch * 16, W + (size_t)(n0w + row) * stride + c * 32 + ch * 8);
    }
}

// ---------------------------------------------------------------------------
// Stage 1 (half K): acc = zp_half[M x 512] @ W1t_half^T.  B: warp-private
// double buffer. A: 6-slot ring in Y overlay, prefetch distance 4, one
// __syncthreads per k32 chunk.
// ---------------------------------------------------------------------------
template <int NMT>
__device__ __forceinline__ void stage1_gemm(
    uint32_t sb, const __nv_bfloat16* __restrict__ Agm,
    const __nv_bfloat16* __restrict__ Bgm,
    float (&acc)[4][4][4], int tid)
{
    const int lane = tid & 31, wn = tid >> 5;
    const uint32_t wb = sb + WB_OFF + wn * 2 * WBUF;
    ZERO_ACC(acc, NMT);

    auto fillA = [&](int s, int c) {
        if (tid < NMT * 64) {   // NMT*16 rows x 4 x 16B units, 1/thread
            const int row = tid >> 2, ch = tid & 3;
            cp16(sb + Y_OFF + s * ASLOT + row * 80 + ch * 16,
                 Agm + (size_t)row * ZPD + c * 32 + ch * 8);
        }
    };

    fillA(0, 0); fillA(1, 1); fillA(2, 2); fillA(3, 3);
    cp_commit();
    fillB_warp(wb, Bgm, ZPD, wn * 32, 0, lane);
    cp_commit();

    #pragma unroll 1
    for (int c = 0; c < 16; c++) {
        if (c + 4 < 16) fillA((c + 4) % 6, c + 4);
        cp_commit();
        if (c + 1 < 16) fillB_warp(wb + ((c + 1) & 1) * WBUF, Bgm, ZPD, wn * 32, c + 1, lane);
        cp_commit();
        asm volatile("cp.async.wait_group 2;" ::: "memory");
        __syncthreads();
        consume_k32<NMT>(sb + Y_OFF + (c % 6) * ASLOT, 80, wb + (c & 1) * WBUF, acc, lane);
    }
}

// ---------------------------------------------------------------------------
// Stages 2-4: A resident in smem (XPITCH rows), B warp-local double buffer.
// NO CTA barriers.
// ---------------------------------------------------------------------------
template <int NMT>
__device__ __forceinline__ void gemm_res(
    uint32_t sb, uint32_t aOff, const __nv_bfloat16* __restrict__ W,
    float (&acc)[4][4][4], int lane, int wn)
{
    ZERO_ACC(acc, NMT);
    const uint32_t wb = sb + WB_OFF + wn * 2 * WBUF;
    const int n0w = wn * 32;

    fillB_warp(wb, W, HID, n0w, 0, lane);
    cp_commit();
    #pragma unroll 1
    for (int c = 0; c < 8; c++) {
        if (c + 1 < 8) {
            fillB_warp(wb + ((c + 1) & 1) * WBUF, W, HID, n0w, c + 1, lane);
            cp_commit();
            asm volatile("cp.async.wait_group 1;" ::: "memory");
        } else {
            asm volatile("cp.async.wait_group 0;" ::: "memory");
        }
        __syncwarp();
        consume_k32<NMT>(sb + aOff + c * 64, XPITCH, wb + (c & 1) * WBUF, acc, lane);
    }
}

#define EPI_BEGIN(NMT)                                                          \
    _Pragma("unroll") for (int mt = 0; mt < NMT; mt++)                          \
    _Pragma("unroll") for (int i2 = 0; i2 < 2; i2++) {                          \
        const int m = mt * 16 + i2 * 8 + (lane >> 2);                           \
        _Pragma("unroll") for (int nt = 0; nt < 4; nt++) {                      \
            const int n = wn * 32 + nt * 8 + 2 * (lane & 3);                    \
            const float v0 = acc[mt][nt][i2 * 2], v1 = acc[mt][nt][i2 * 2 + 1];
#define EPI_END }}

// ---------------------------------------------------------------------------
// Leapfrog body: one CTA owns NMT*16 batch rows.  it8 (step-3 p-update) is
// provably dead for the output (out = q) and is skipped; it7's q-update
// writes straight to out.
// ---------------------------------------------------------------------------
template <int NMT>
__device__ __forceinline__ void leapfrog_body(
    uint32_t sb, char* smem, int m0,
    const float* __restrict__ b1, const float* __restrict__ b2,
    const float* __restrict__ W3, float* __restrict__ out)
{
    const int tid = threadIdx.x, lane = tid & 31, wn = tid >> 5;
    float acc[4][4][4];

    #pragma unroll 1
    for (int it = 0; it < 8; it++) {
        const int call = it - (it / 3) * 3;
        const int qpOff   = (call == 1) ? DIMQ : 0;
        const int colBase = (call == 1) ? 0 : DIMQ;
        const float coef  = (call == 1) ? DTC : -0.5f * DTC;
        const int rec = (it == 0) ? 0 : ((call == 2) ? 0 : 1);   // 0 = q-half, 1 = p-half
        const int cOff = rec ? DIMQ : 0;
        const bool last = (it == 7);

        // Stage 1 (half K): fresh = zp_half @ W1_half
        stage1_gemm<NMT>(sb, g_zpb + (size_t)m0 * ZPD + cOff, g_W1t + cOff, acc, tid);
        {
            float* recS = rec ? g_Sp : g_Sq;
            const float* othS = rec ? g_Sq : g_Sp;      // it==0: unused (Sp==0)
            const bool useOth = (it != 0);
            EPI_BEGIN(NMT)
                const size_t o = (size_t)(m0 + m) * HID + n;
                if (!last) *(float2*)(recS + o) = make_float2(v0, v1);
                float c0 = 0.f, c1 = 0.f;
                if (useOth) { const float2 cc = *(const float2*)(othS + o); c0 = cc.x; c1 = cc.y; }
                const float t0 = tanh_fast(v0 + c0 + __ldg(b1 + n));
                const float t1 = tanh_fast(v1 + c1 + __ldg(b1 + n + 1));
                *(__nv_bfloat162*)(smem + X_OFF + m * XPITCH + n * 2) = pack_bf2(t0, t1);
            EPI_END
        }
        __syncthreads();

        // Stage 2: d2 = (1 - tanh(h1@W2 + b2)^2) * W3 -> Y
        gemm_res<NMT>(sb, X_OFF, g_W2t, acc, lane, wn);
        EPI_BEGIN(NMT)
            const float t0 = tanh_fast(v0 + __ldg(b2 + n));
            const float t1 = tanh_fast(v1 + __ldg(b2 + n + 1));
            const float r0 = (1.0f - t0 * t0) * __ldg(W3 + n);
            const float r1 = (1.0f - t1 * t1) * __ldg(W3 + n + 1);
            *(__nv_bfloat162*)(smem + Y_OFF + m * XPITCH + n * 2) = pack_bf2(r0, r1);
        EPI_END
        __syncthreads();

        // Stage 3: d1 = (d2 @ W2^T) * (1 - h1^2) -> X in-place (owner rmw)
        gemm_res<NMT>(sb, Y_OFF, g_W2d, acc, lane, wn);
        EPI_BEGIN(NMT)
            __nv_bfloat162* xp = (__nv_bfloat162*)(smem + X_OFF + m * XPITCH + n * 2);
            const __nv_bfloat162 hh = *xp;
            const float h0 = __bfloat162float(hh.x), h1v = __bfloat162float(hh.y);
            *xp = pack_bf2(v0 * (1.0f - h0 * h0), v1 * (1.0f - h1v * h1v));
        EPI_END
        __syncthreads();

        // Stage 4: g-half = d1 @ W1[qpOff..]^T, fused leapfrog zp update.
        // it7 (final q-update): write result directly to out; no zp/zpb upkeep.
        #pragma unroll 1
        for (int pass = 0; pass < 2; pass++) {
            gemm_res<NMT>(sb, X_OFF, g_W1d + (size_t)(qpOff + pass * 256) * HID, acc, lane, wn);
            if (last) {
                EPI_BEGIN(NMT)
                    const size_t o = (size_t)(m0 + m) * ZPD + pass * 256 + n;   // colBase = 0
                    float2 z = *(float2*)(g_zp + o);
                    z.x += coef * v0;
                    z.y += coef * v1;
                    *(float2*)(out + (size_t)(m0 + m) * DIMQ + pass * 256 + n) = z;
                EPI_END
            } else {
                EPI_BEGIN(NMT)
                    const size_t o = (size_t)(m0 + m) * ZPD + colBase + pass * 256 + n;
                    float2 z = *(float2*)(g_zp + o);
                    z.x += coef * v0;
                    z.y += coef * v1;
                    *(float2*)(g_zp + o) = z;
                    *(__nv_bfloat162*)(g_zpb + o) = pack_bf2(z.x, z.y);
                EPI_END
            }
        }
        __syncthreads();   // call boundary: zp/zpb visible to next stage 1
    }
}

__global__ void __launch_bounds__(256, 2) leapfrog_all(
    const float* __restrict__ b1, const float* __restrict__ b2,
    const float* __restrict__ W3, float* __restrict__ out)
{
    extern __shared__ char smem[];
    const uint32_t sb = smem_u32(smem);
    const int bx = blockIdx.x;
    if (bx < N64CTAS) {
        leapfrog_body<4>(sb, smem, bx * 64, b1, b2, W3, out);
    } else {
        leapfrog_body<3>(sb, smem, N64CTAS * 64 + (bx - N64CTAS) * 48, b1, b2, W3, out);
    }
}

// ---------------- small kernels ----------------
__global__ void __launch_bounds__(256) prep_weights(const float* __restrict__ W1,
                                                    const float* __restrict__ W2)
{
    const int idx = blockIdx.x * 256 + threadIdx.x;     // 0 .. 262143
    {
        const int k = idx >> 8, n = idx & 255;
        const __nv_bfloat16 v = __float2bfloat16_rn(W1[idx]);
        g_W1d[idx] = v;
        g_W1t[n * ZPD + k] = v;
    }
    if (idx < HID * HID) {
        const int k = idx >> 8, n = idx & 255;
        const __nv_bfloat16 v = __float2bfloat16_rn(W2[idx]);
        g_W2d[idx] = v;
        g_W2t[n * HID + k] = v;
    }
}

__global__ void __launch_bounds__(256) init_zp(const float* __restrict__ z)
{
    const int i = blockIdx.x * 256 + threadIdx.x;       // over BATCH*DIMQ/4
    const int m = i / (DIMQ / 4);
    const int c = (i % (DIMQ / 4)) * 4;
    const float4 zv = *(const float4*)&z[(size_t)m * DIMQ + c];
    const size_t oq = (size_t)m * ZPD + c;
    const size_t op = oq + DIMQ;
    *(float4*)&g_zp[oq] = zv;
    *(float4*)&g_zp[op] = make_float4(0.f, 0.f, 0.f, 0.f);
    __nv_bfloat162 b01 = pack_bf2(zv.x, zv.y), b23 = pack_bf2(zv.z, zv.w);
    *(uint2*)&g_zpb[oq] = make_uint2(*(uint32_t*)&b01, *(uint32_t*)&b23);
    *(uint2*)&g_zpb[op] = make_uint2(0u, 0u);
}

// ---------------- launcher ----------------
extern "C" void kernel_launch(void* const* d_in, const int* in_sizes, int n_in,
                              void* d_out, int out_size)
{
    const float* z  = (const float*)d_in[0];
    const float* W1 = (const float*)d_in[1];
    const float* b1 = (const float*)d_in[2];
    const float* W2 = (const float*)d_in[3];
    const float* b2 = (const float*)d_in[4];
    const float* W3 = (const float*)d_in[5];
    // d_in[6] = b3: constant, no gradient contribution.
    float* out = (float*)d_out;

    cudaFuncSetAttribute(leapfrog_all, cudaFuncAttributeMaxDynamicSharedMemorySize, SMEM_SZ);

    const dim3 blk(256);
    const dim3 grid_cp((BATCH * DIMQ / 4) / 256);

    init_zp<<<grid_cp, blk>>>(z);
    prep_weights<<<ZPD * HID / 256, blk>>>(W1, W2);
    leapfrog_all<<<NGRID, blk, SMEM_SZ>>>(b1, b2, W3, out);
}

// round 14
// speedup vs baseline: 1.8049x; 1.0365x over previous
#include <cuda_runtime.h>
#include <cuda_bf16.h>
#include <stdint.h>

#define BATCH 16384
#define DIMQ  512
#define ZPD   1024
#define HID   256
#define DTC   0.1f

// grid: 136 CTAs x 64 rows + 160 CTAs x 48 rows = 296 CTAs = 2 x 148 SMs
#define N64CTAS 136
#define NGRID   296

#define XPITCH 528                        // 256 bf16 = 512B + 16B pad (ldsm conflict-free)
#define X_OFF 0                           // h1, then d1 (in-place)
#define XSZ (64 * XPITCH)                 // 33792 (sized for max 64 rows)
#define Y_OFF XSZ                         // d2; stage-1 A ring overlay (6 x 5120 = 30720)
#define ASLOT 5120                        // 64 rows x 80B
#define WB_OFF (2 * XSZ)                  // 67584: per-warp B buffers
#define WBUF 2560                         // 32 rows x 80B
#define SMEM_SZ (WB_OFF + 8 * 2 * WBUF)   // 108544 -> 2 CTAs/SM

// ---------------- device globals (no allocs allowed) ----------------
__device__ float         g_zp [BATCH * ZPD];     // fp32 master [q|p]
__device__ __nv_bfloat16 g_zpb[BATCH * ZPD];     // bf16 mirror (MMA operand)
__device__ float         g_Sq [BATCH * HID];     // cache: q @ W1[:512]
__device__ float         g_Sp [BATCH * HID];     // cache: p @ W1[512:]
__device__ __nv_bfloat16 g_W1t[HID * ZPD];       // W1^T [256][1024]
__device__ __nv_bfloat16 g_W1d[ZPD * HID];       // W1   [1024][256]
__device__ __nv_bfloat16 g_W2t[HID * HID];       // W2^T
__device__ __nv_bfloat16 g_W2d[HID * HID];       // W2

// ---------------- helpers ----------------
__device__ __forceinline__ uint32_t smem_u32(const void* p) {
    uint32_t a;
    asm("{ .reg .u64 t; cvta.to.shared.u64 t, %1; cvt.u32.u64 %0, t; }" : "=r"(a) : "l"(p));
    return a;
}
__device__ __forceinline__ float tanh_fast(float x) {
    float y; asm("tanh.approx.f32 %0, %1;" : "=f"(y) : "f"(x)); return y;
}
__device__ __forceinline__ void cp16(uint32_t s, const void* g) {
    asm volatile("cp.async.cg.shared.global [%0], [%1], 16;" :: "r"(s), "l"(g) : "memory");
}
__device__ __forceinline__ void cp_commit() {
    asm volatile("cp.async.commit_group;" ::: "memory");
}
__device__ __forceinline__ void ldsm4(uint32_t* r, uint32_t a) {
    asm volatile("ldmatrix.sync.aligned.m8n8.x4.shared.b16 {%0,%1,%2,%3}, [%4];"
                 : "=r"(r[0]), "=r"(r[1]), "=r"(r[2]), "=r"(r[3]) : "r"(a));
}
__device__ __forceinline__ void mma16816(float* c, const uint32_t* a, const uint32_t* b) {
    asm volatile("mma.sync.aligned.m16n8k16.row.col.f32.bf16.bf16.f32 "
                 "{%0,%1,%2,%3}, {%4,%5,%6,%7}, {%8,%9}, {%0,%1,%2,%3};"
                 : "+f"(c[0]), "+f"(c[1]), "+f"(c[2]), "+f"(c[3])
                 : "r"(a[0]), "r"(a[1]), "r"(a[2]), "r"(a[3]), "r"(b[0]), "r"(b[1]));
}
__device__ __forceinline__ __nv_bfloat162 pack_bf2(float a, float b) {
    return __halves2bfloat162(__float2bfloat16_rn(a), __float2bfloat16_rn(b));
}

#define ZERO_ACC(acc, NMT)                                                      \
    _Pragma("unroll") for (int _i = 0; _i < NMT; _i++)                          \
    _Pragma("unroll") for (int _j = 0; _j < 4; _j++)                            \
    _Pragma("unroll") for (int _d = 0; _d < 4; _d++) (acc)[_i][_j][_d] = 0.f;

// consume one k32 chunk: A NMT*16 rows from (abase, apitch), B warp slice (80B rows)
template <int NMT>
__device__ __forceinline__ void consume_k32(
    uint32_t abase, int apitch, uint32_t bbase,
    float (&acc)[4][4][4], int lane)
{
    #pragma unroll
    for (int kt = 0; kt < 2; kt++) {
        uint32_t a[NMT][4], b[2][4];
        #pragma unroll
        for (int mt = 0; mt < NMT; mt++)
            ldsm4(a[mt], abase + (mt * 16 + (lane & 15)) * apitch
                          + ((lane >> 4) << 4) + kt * 32);
        #pragma unroll
        for (int p = 0; p < 2; p++)
            ldsm4(b[p], bbase + (p * 16 + ((lane >> 4) << 3) + (lane & 7)) * 80
                         + (((lane >> 3) & 1) << 4) + kt * 32);
        #pragma unroll
        for (int mt = 0; mt < NMT; mt++)
            #pragma unroll
            for (int p = 0; p < 2; p++) {
                mma16816(acc[mt][2 * p],     a[mt], &b[p][0]);
                mma16816(acc[mt][2 * p + 1], a[mt], &b[p][2]);
            }
    }
}

// fill warp-private B slot: 32 weight rows x one k32 chunk (128 16B units, 4/lane)
__device__ __forceinline__ void fillB_warp(uint32_t stg, const __nv_bfloat16* __restrict__ W,
                                           int stride, int n0w, int c, int lane)
{
    #pragma unroll
    for (int r = 0; r < 4; r++) {
        const int u = r * 32 + lane;
        const int row = u >> 2, ch = u & 3;
        cp16(stg + row * 80 + ch * 16, W + (size_t)(n0w + row) * stride + c * 32 + ch * 8);
    }
}

// ---------------------------------------------------------------------------
// Stage 1 (half K): acc = zp_half[M x 512] @ W1t_half^T.
// ENTRY CONTRACT: this stage's B chunk0 is already in buf0 (one pending group).
// Per iter: commit B(c+1) first, then A(c+4)  -> wait_group 3 forces only B(c)
// (and A(c+2)), preserving true A prefetch distance.  Last iter pre-issues the
// NEXT segment's B chunk0 into the just-freed buf0.
// ---------------------------------------------------------------------------
template <int NMT>
__device__ __forceinline__ void stage1_gemm(
    uint32_t sb, const __nv_bfloat16* __restrict__ Agm,
    const __nv_bfloat16* __restrict__ Bgm,      // W1t + cOff
    const __nv_bfloat16* __restrict__ Bnext,    // next segment's weights
    float (&acc)[4][4][4], int tid)
{
    const int lane = tid & 31, wn = tid >> 5;
    const uint32_t wb = sb + WB_OFF + wn * 2 * WBUF;
    ZERO_ACC(acc, NMT);

    auto fillA = [&](int s, int c) {
        if (tid < NMT * 64) {   // NMT*16 rows x 4 x 16B units, 1/thread
            const int row = tid >> 2, ch = tid & 3;
            cp16(sb + Y_OFF + s * ASLOT + row * 80 + ch * 16,
                 Agm + (size_t)row * ZPD + c * 32 + ch * 8);
        }
    };

    fillA(0, 0); fillA(1, 1); fillA(2, 2); fillA(3, 3);
    cp_commit();

    #pragma unroll 1
    for (int c = 0; c < 16; c++) {
        // B commit first (so waiting for B(c) doesn't force fresh A groups)
        if (c + 1 < 16) fillB_warp(wb + ((c + 1) & 1) * WBUF, Bgm, ZPD, wn * 32, c + 1, lane);
        else            fillB_warp(wb + ((c + 1) & 1) * WBUF, Bnext, HID, wn * 32, 0, lane);
        cp_commit();
        if (c + 4 < 16) fillA((c + 4) % 6, c + 4);
        cp_commit();
        if (c == 0) asm volatile("cp.async.wait_group 2;" ::: "memory");
        else        asm volatile("cp.async.wait_group 3;" ::: "memory");
        __syncthreads();
        consume_k32<NMT>(sb + Y_OFF + (c % 6) * ASLOT, 80, wb + (c & 1) * WBUF, acc, lane);
    }
}

// ---------------------------------------------------------------------------
// Stages 2-4: A resident in smem (XPITCH rows), B warp-local double buffer.
// ENTRY CONTRACT: B chunk0 already pending in buf0.  Last iter pre-issues the
// next segment's B chunk0 (stride nextStride).  NO CTA barriers.
// ---------------------------------------------------------------------------
template <int NMT>
__device__ __forceinline__ void gemm_res(
    uint32_t sb, uint32_t aOff, const __nv_bfloat16* __restrict__ W,
    const __nv_bfloat16* __restrict__ Wnext, int nextStride,
    float (&acc)[4][4][4], int lane, int wn)
{
    ZERO_ACC(acc, NMT);
    const uint32_t wb = sb + WB_OFF + wn * 2 * WBUF;
    const int n0w = wn * 32;

    #pragma unroll 1
    for (int c = 0; c < 8; c++) {
        if (c + 1 < 8) fillB_warp(wb + ((c + 1) & 1) * WBUF, W, HID, n0w, c + 1, lane);
        else           fillB_warp(wb + ((c + 1) & 1) * WBUF, Wnext, nextStride, n0w, 0, lane);
        cp_commit();
        asm volatile("cp.async.wait_group 1;" ::: "memory");
        __syncwarp();
        consume_k32<NMT>(sb + aOff + c * 64, XPITCH, wb + (c & 1) * WBUF, acc, lane);
    }
}

#define EPI_BEGIN(NMT)                                                          \
    _Pragma("unroll") for (int mt = 0; mt < NMT; mt++)                          \
    _Pragma("unroll") for (int i2 = 0; i2 < 2; i2++) {                          \
        const int m = mt * 16 + i2 * 8 + (lane >> 2);                           \
        _Pragma("unroll") for (int nt = 0; nt < 4; nt++) {                      \
            const int n = wn * 32 + nt * 8 + 2 * (lane & 3);                    \
            const float v0 = acc[mt][nt][i2 * 2], v1 = acc[mt][nt][i2 * 2 + 1];
#define EPI_END }}

// ---------------------------------------------------------------------------
// Leapfrog body: one CTA owns NMT*16 batch rows.  it8 dead-code eliminated;
// it7 writes q straight to out.  B operands chained across ALL segment
// boundaries so no segment starts with a cold L2 round trip.
// ---------------------------------------------------------------------------
template <int NMT>
__device__ __forceinline__ void leapfrog_body(
    uint32_t sb, char* smem, int m0,
    const float* __restrict__ b1, const float* __restrict__ b2,
    const float* __restrict__ W3, float* __restrict__ out)
{
    const int tid = threadIdx.x, lane = tid & 31, wn = tid >> 5;
    const uint32_t wb = sb + WB_OFF + wn * 2 * WBUF;
    float acc[4][4][4];

    // prime the chain: it0 stage1's B chunk0 (W1t, cOff=0)
    fillB_warp(wb, g_W1t, ZPD, wn * 32, 0, lane);
    cp_commit();

    #pragma unroll 1
    for (int it = 0; it < 8; it++) {
        const int call = it - (it / 3) * 3;
        const int qpOff   = (call == 1) ? DIMQ : 0;
        const int colBase = (call == 1) ? 0 : DIMQ;
        const float coef  = (call == 1) ? DTC : -0.5f * DTC;
        const int rec = (it == 0) ? 0 : ((call == 2) ? 0 : 1);   // 0 = q-half, 1 = p-half
        const int cOff = rec ? DIMQ : 0;
        const bool last = (it == 7);
        // next it's stage-1 W1t half (for cross-it B chaining); it7: dummy (unused)
        const int cOffN = (((it + 1) % 3) == 2) ? 0 : DIMQ;

        // Stage 1 (half K): fresh = zp_half @ W1_half   [chains B -> W2t]
        stage1_gemm<NMT>(sb, g_zpb + (size_t)m0 * ZPD + cOff, g_W1t + cOff,
                         g_W2t, acc, tid);
        {
            float* recS = rec ? g_Sp : g_Sq;
            const float* othS = rec ? g_Sq : g_Sp;      // it==0: unused (Sp==0)
            const bool useOth = (it != 0);
            EPI_BEGIN(NMT)
                const size_t o = (size_t)(m0 + m) * HID + n;
                if (!last) *(float2*)(recS + o) = make_float2(v0, v1);
                float c0 = 0.f, c1 = 0.f;
                if (useOth) { const float2 cc = *(const float2*)(othS + o); c0 = cc.x; c1 = cc.y; }
                const float t0 = tanh_fast(v0 + c0 + __ldg(b1 + n));
                const float t1 = tanh_fast(v1 + c1 + __ldg(b1 + n + 1));
                *(__nv_bfloat162*)(smem + X_OFF + m * XPITCH + n * 2) = pack_bf2(t0, t1);
            EPI_END
        }
        __syncthreads();

        // Stage 2: d2 = (1 - tanh(h1@W2 + b2)^2) * W3 -> Y   [chains B -> W2d]
        gemm_res<NMT>(sb, X_OFF, g_W2t, g_W2d, HID, acc, lane, wn);
        EPI_BEGIN(NMT)
            const float t0 = tanh_fast(v0 + __ldg(b2 + n));
            const float t1 = tanh_fast(v1 + __ldg(b2 + n + 1));
            const float r0 = (1.0f - t0 * t0) * __ldg(W3 + n);
            const float r1 = (1.0f - t1 * t1) * __ldg(W3 + n + 1);
            *(__nv_bfloat162*)(smem + Y_OFF + m * XPITCH + n * 2) = pack_bf2(r0, r1);
        EPI_END
        __syncthreads();

        // Stage 3: d1 = (d2 @ W2^T) * (1 - h1^2) -> X in-place   [chains -> W1d p0]
        gemm_res<NMT>(sb, Y_OFF, g_W2d, g_W1d + (size_t)qpOff * HID, HID, acc, lane, wn);
        EPI_BEGIN(NMT)
            __nv_bfloat162* xp = (__nv_bfloat162*)(smem + X_OFF + m * XPITCH + n * 2);
            const __nv_bfloat162 hh = *xp;
            const float h0 = __bfloat162float(hh.x), h1v = __bfloat162float(hh.y);
            *xp = pack_bf2(v0 * (1.0f - h0 * h0), v1 * (1.0f - h1v * h1v));
        EPI_END
        __syncthreads();

        // Stage 4: g-half = d1 @ W1[qpOff..]^T, fused leapfrog zp update.
        #pragma unroll 1
        for (int pass = 0; pass < 2; pass++) {
            const __nv_bfloat16* Wcur = g_W1d + (size_t)(qpOff + pass * 256) * HID;
            const __nv_bfloat16* Wnxt = (pass == 0)
                ? g_W1d + (size_t)(qpOff + 256) * HID    // this stage's pass 2
                : g_W1t + cOffN;                          // next it's stage 1
            const int nstride = (pass == 0) ? HID : ZPD;
            gemm_res<NMT>(sb, X_OFF, Wcur, Wnxt, nstride, acc, lane, wn);
            if (last) {
                EPI_BEGIN(NMT)
                    const size_t o = (size_t)(m0 + m) * ZPD + pass * 256 + n;   // colBase = 0
                    float2 z = *(float2*)(g_zp + o);
                    z.x += coef * v0;
                    z.y += coef * v1;
                    *(float2*)(out + (size_t)(m0 + m) * DIMQ + pass * 256 + n) = z;
                EPI_END
            } else if (it == 0) {
                // p == 0 before the first half-kick: pure write, no g_zp read
                EPI_BEGIN(NMT)
                    const size_t o = (size_t)(m0 + m) * ZPD + colBase + pass * 256 + n;
                    const float zx = coef * v0, zy = coef * v1;
                    *(float2*)(g_zp + o) = make_float2(zx, zy);
                    *(__nv_bfloat162*)(g_zpb + o) = pack_bf2(zx, zy);
                EPI_END
            } else {
                EPI_BEGIN(NMT)
                    const size_t o = (size_t)(m0 + m) * ZPD + colBase + pass * 256 + n;
                    float2 z = *(float2*)(g_zp + o);
                    z.x += coef * v0;
                    z.y += coef * v1;
                    *(float2*)(g_zp + o) = z;
                    *(__nv_bfloat162*)(g_zpb + o) = pack_bf2(z.x, z.y);
                EPI_END
            }
        }
        __syncthreads();   // call boundary: zp/zpb visible to next stage 1
    }
}

__global__ void __launch_bounds__(256, 2) leapfrog_all(
    const float* __restrict__ b1, const float* __restrict__ b2,
    const float* __restrict__ W3, float* __restrict__ out)
{
    extern __shared__ char smem[];
    const uint32_t sb = smem_u32(smem);
    const int bx = blockIdx.x;
    if (bx < N64CTAS) {
        leapfrog_body<4>(sb, smem, bx * 64, b1, b2, W3, out);
    } else {
        leapfrog_body<3>(sb, smem, N64CTAS * 64 + (bx - N64CTAS) * 48, b1, b2, W3, out);
    }
}

// ---------------- small kernels ----------------
__global__ void __launch_bounds__(256) prep_weights(const float* __restrict__ W1,
                                                    const float* __restrict__ W2)
{
    const int idx = blockIdx.x * 256 + threadIdx.x;     // 0 .. 262143
    {
        const int k = idx >> 8, n = idx & 255;
        const __nv_bfloat16 v = __float2bfloat16_rn(W1[idx]);
        g_W1d[idx] = v;
        g_W1t[n * ZPD + k] = v;
    }
    if (idx < HID * HID) {
        const int k = idx >> 8, n = idx & 255;
        const __nv_bfloat16 v = __float2bfloat16_rn(W2[idx]);
        g_W2d[idx] = v;
        g_W2t[n * HID + k] = v;
    }
}

// q-halves only: p-halves of g_zp / g_zpb are written by it0's stage 4
// before any read (p == 0 initially, and it0's p-update is a pure write).
__global__ void __launch_bounds__(256) init_zp(const float* __restrict__ z)
{
    const int i = blockIdx.x * 256 + threadIdx.x;       // over BATCH*DIMQ/4
    const int m = i / (DIMQ / 4);
    const int c = (i % (DIMQ / 4)) * 4;
    const float4 zv = *(const float4*)&z[(size_t)m * DIMQ + c];
    const size_t oq = (size_t)m * ZPD + c;
    *(float4*)&g_zp[oq] = zv;
    __nv_bfloat162 b01 = pack_bf2(zv.x, zv.y), b23 = pack_bf2(zv.z, zv.w);
    *(uint2*)&g_zpb[oq] = make_uint2(*(uint32_t*)&b01, *(uint32_t*)&b23);
}

// ---------------- launcher ----------------
extern "C" void kernel_launch(void* const* d_in, const int* in_sizes, int n_in,
                              void* d_out, int out_size)
{
    const float* z  = (const float*)d_in[0];
    const float* W1 = (const float*)d_in[1];
    const float* b1 = (const float*)d_in[2];
    const float* W2 = (const float*)d_in[3];
    const float* b2 = (const float*)d_in[4];
    const float* W3 = (const float*)d_in[5];
    // d_in[6] = b3: constant, no gradient contribution.
    float* out = (float*)d_out;

    cudaFuncSetAttribute(leapfrog_all, cudaFuncAttributeMaxDynamicSharedMemorySize, SMEM_SZ);

    const dim3 blk(256);
    const dim3 grid_cp((BATCH * DIMQ / 4) / 256);

    init_zp<<<grid_cp, blk>>>(z);
    prep_weights<<<ZPD * HID / 256, blk>>>(W1, W2);
    leapfrog_all<<<NGRID, blk, SMEM_SZ>>>(b1, b2, W3, out);
}

// round 15
// speedup vs baseline: 1.8099x; 1.0028x over previous
#include <cuda_runtime.h>
#include <cuda_bf16.h>
#include <stdint.h>

#define BATCH 16384
#define DIMQ  512
#define ZPD   1024
#define HID   256
#define DTC   0.1f

// grid: 136 CTAs x 64 rows + 160 CTAs x 48 rows = 296 CTAs = 2 x 148 SMs
#define N64CTAS 136
#define NGRID   296

#define XPITCH 528                        // 256 bf16 = 512B + 16B pad (ldsm conflict-free)
#define X_OFF 0                           // h1, then d1 (in-place)
#define XSZ (64 * XPITCH)                 // 33792 (sized for max 64 rows)
#define Y_OFF XSZ                         // d2; stage-1 A ring overlay (6 x 5120 = 30720)
#define ASLOT 5120                        // 64 rows x 80B
#define WB_OFF (2 * XSZ)                  // 67584: per-warp B buffers
#define WBUF 2560                         // 32 rows x 80B
#define SMEM_SZ (WB_OFF + 8 * 2 * WBUF)   // 108544 -> 2 CTAs/SM

// ---------------- device globals (no allocs allowed) ----------------
__device__ float         g_zp [BATCH * ZPD];     // fp32 master [q|p]
__device__ __nv_bfloat16 g_zpb[BATCH * ZPD];     // bf16 mirror (MMA operand)
__device__ float         g_Sq [BATCH * HID];     // cache: q @ W1[:512]
__device__ float         g_Sp [BATCH * HID];     // cache: p @ W1[512:]
__device__ __nv_bfloat16 g_W1t[HID * ZPD];       // W1^T [256][1024]
__device__ __nv_bfloat16 g_W1d[ZPD * HID];       // W1   [1024][256]
__device__ __nv_bfloat16 g_W2t[HID * HID];       // W2^T
__device__ __nv_bfloat16 g_W2d[HID * HID];       // W2

// ---------------- helpers ----------------
__device__ __forceinline__ uint32_t smem_u32(const void* p) {
    uint32_t a;
    asm("{ .reg .u64 t; cvta.to.shared.u64 t, %1; cvt.u32.u64 %0, t; }" : "=r"(a) : "l"(p));
    return a;
}
__device__ __forceinline__ float tanh_fast(float x) {
    float y; asm("tanh.approx.f32 %0, %1;" : "=f"(y) : "f"(x)); return y;
}
__device__ __forceinline__ void cp16(uint32_t s, const void* g) {
    asm volatile("cp.async.cg.shared.global [%0], [%1], 16;" :: "r"(s), "l"(g) : "memory");
}
__device__ __forceinline__ void cp_commit() {
    asm volatile("cp.async.commit_group;" ::: "memory");
}
__device__ __forceinline__ void ldsm4(uint32_t* r, uint32_t a) {
    asm volatile("ldmatrix.sync.aligned.m8n8.x4.shared.b16 {%0,%1,%2,%3}, [%4];"
                 : "=r"(r[0]), "=r"(r[1]), "=r"(r[2]), "=r"(r[3]) : "r"(a));
}
__device__ __forceinline__ void mma16816(float* c, const uint32_t* a, const uint32_t* b) {
    asm volatile("mma.sync.aligned.m16n8k16.row.col.f32.bf16.bf16.f32 "
                 "{%0,%1,%2,%3}, {%4,%5,%6,%7}, {%8,%9}, {%0,%1,%2,%3};"
                 : "+f"(c[0]), "+f"(c[1]), "+f"(c[2]), "+f"(c[3])
                 : "r"(a[0]), "r"(a[1]), "r"(a[2]), "r"(a[3]), "r"(b[0]), "r"(b[1]));
}
__device__ __forceinline__ __nv_bfloat162 pack_bf2(float a, float b) {
    return __halves2bfloat162(__float2bfloat16_rn(a), __float2bfloat16_rn(b));
}

#define ZERO_ACC(acc, NMT)                                                      \
    _Pragma("unroll") for (int _i = 0; _i < NMT; _i++)                          \
    _Pragma("unroll") for (int _j = 0; _j < 4; _j++)                            \
    _Pragma("unroll") for (int _d = 0; _d < 4; _d++) (acc)[_i][_j][_d] = 0.f;

// consume one k32 chunk: A NMT*16 rows from (abase, apitch), B warp slice (80B rows)
template <int NMT>
__device__ __forceinline__ void consume_k32(
    uint32_t abase, int apitch, uint32_t bbase,
    float (&acc)[4][4][4], int lane)
{
    #pragma unroll
    for (int kt = 0; kt < 2; kt++) {
        uint32_t a[NMT][4], b[2][4];
        #pragma unroll
        for (int mt = 0; mt < NMT; mt++)
            ldsm4(a[mt], abase + (mt * 16 + (lane & 15)) * apitch
                          + ((lane >> 4) << 4) + kt * 32);
        #pragma unroll
        for (int p = 0; p < 2; p++)
            ldsm4(b[p], bbase + (p * 16 + ((lane >> 4) << 3) + (lane & 7)) * 80
                         + (((lane >> 3) & 1) << 4) + kt * 32);
        #pragma unroll
        for (int mt = 0; mt < NMT; mt++)
            #pragma unroll
            for (int p = 0; p < 2; p++) {
                mma16816(acc[mt][2 * p],     a[mt], &b[p][0]);
                mma16816(acc[mt][2 * p + 1], a[mt], &b[p][2]);
            }
    }
}

// fill warp-private B slot: 32 weight rows x one k32 chunk (128 16B units, 4/lane)
__device__ __forceinline__ void fillB_warp(uint32_t stg, const __nv_bfloat16* __restrict__ W,
                                           int stride, int n0w, int c, int lane)
{
    #pragma unroll
    for (int r = 0; r < 4; r++) {
        const int u = r * 32 + lane;
        const int row = u >> 2, ch = u & 3;
        cp16(stg + row * 80 + ch * 16, W + (size_t)(n0w + row) * stride + c * 32 + ch * 8);
    }
}

// ---------------------------------------------------------------------------
// Stage 1 (half K): acc = zp_half[M x 512] @ W1t_half^T.
// ENTRY CONTRACT: this stage's B chunk0 already pending (chained).
// Order per iter: wait_group 1 -> barrier -> fills -> consume.
// Retirement happens BEFORE the publishing barrier; CTA barrier only every
// other iter (slot-reuse: fill at iter c overwrites slot last read at c-2,
// guaranteed complete by the alternating barrier).  A prefetch slack: 4 iters.
// Last iter pre-issues the NEXT segment's B chunk0 into the freed buffer.
// ---------------------------------------------------------------------------
template <int NMT>
__device__ __forceinline__ void stage1_gemm(
    uint32_t sb, const __nv_bfloat16* __restrict__ Agm,
    const __nv_bfloat16* __restrict__ Bgm,      // W1t + cOff
    const __nv_bfloat16* __restrict__ Bnext,    // next segment's weights
    float (&acc)[4][4][4], int tid)
{
    const int lane = tid & 31, wn = tid >> 5;
    const uint32_t wb = sb + WB_OFF + wn * 2 * WBUF;
    ZERO_ACC(acc, NMT);

    auto fillA = [&](int s, int c) {
        if (tid < NMT * 64) {   // NMT*16 rows x 4 x 16B units, 1/thread
            const int row = tid >> 2, ch = tid & 3;
            cp16(sb + Y_OFF + s * ASLOT + row * 80 + ch * 16,
                 Agm + (size_t)row * ZPD + c * 32 + ch * 8);
        }
    };

    // prologue: A0 alone (so wait_group 1 at c=0 forces it), then A1..3
    fillA(0, 0); cp_commit();
    fillA(1, 1); fillA(2, 2); fillA(3, 3); cp_commit();

    #pragma unroll 1
    for (int c = 0; c < 16; c++) {
        asm volatile("cp.async.wait_group 1;" ::: "memory");
        if ((c & 1) == 0) __syncthreads();
        else              __syncwarp();
        if (c + 1 < 16) fillB_warp(wb + ((c + 1) & 1) * WBUF, Bgm, ZPD, wn * 32, c + 1, lane);
        else            fillB_warp(wb + ((c + 1) & 1) * WBUF, Bnext, HID, wn * 32, 0, lane);
        cp_commit();
        if (c + 4 < 16) fillA((c + 4) % 6, c + 4);
        cp_commit();
        consume_k32<NMT>(sb + Y_OFF + (c % 6) * ASLOT, 80, wb + (c & 1) * WBUF, acc, lane);
    }
}

// ---------------------------------------------------------------------------
// Stages 2-4: A resident in smem (XPITCH rows), B warp-local double buffer.
// ENTRY CONTRACT: B chunk0 already pending.  Last iter pre-issues the next
// segment's B chunk0 (stride nextStride).  NO CTA barriers.
// ---------------------------------------------------------------------------
template <int NMT>
__device__ __forceinline__ void gemm_res(
    uint32_t sb, uint32_t aOff, const __nv_bfloat16* __restrict__ W,
    const __nv_bfloat16* __restrict__ Wnext, int nextStride,
    float (&acc)[4][4][4], int lane, int wn)
{
    ZERO_ACC(acc, NMT);
    const uint32_t wb = sb + WB_OFF + wn * 2 * WBUF;
    const int n0w = wn * 32;

    #pragma unroll 1
    for (int c = 0; c < 8; c++) {
        if (c + 1 < 8) fillB_warp(wb + ((c + 1) & 1) * WBUF, W, HID, n0w, c + 1, lane);
        else           fillB_warp(wb + ((c + 1) & 1) * WBUF, Wnext, nextStride, n0w, 0, lane);
        cp_commit();
        asm volatile("cp.async.wait_group 1;" ::: "memory");
        __syncwarp();
        consume_k32<NMT>(sb + aOff + c * 64, XPITCH, wb + (c & 1) * WBUF, acc, lane);
    }
}

#define EPI_BEGIN(NMT)                                                          \
    _Pragma("unroll") for (int mt = 0; mt < NMT; mt++)                          \
    _Pragma("unroll") for (int i2 = 0; i2 < 2; i2++) {                          \
        const int m = mt * 16 + i2 * 8 + (lane >> 2);                           \
        _Pragma("unroll") for (int nt = 0; nt < 4; nt++) {                      \
            const int n = wn * 32 + nt * 8 + 2 * (lane & 3);                    \
            const float v0 = acc[mt][nt][i2 * 2], v1 = acc[mt][nt][i2 * 2 + 1];
#define EPI_END }}

// ---------------------------------------------------------------------------
// Leapfrog body: one CTA owns NMT*16 batch rows.  Per-CTA zp init from z in
// the prologue (rows are CTA-private).  it8 dead-code eliminated; it7 writes
// q straight to out.  B operands chained across ALL segment boundaries.
// ---------------------------------------------------------------------------
template <int NMT>
__device__ __forceinline__ void leapfrog_body(
    uint32_t sb, char* smem, int m0, const float* __restrict__ z,
    const float* __restrict__ b1, const float* __restrict__ b2,
    const float* __restrict__ W3, float* __restrict__ out)
{
    const int tid = threadIdx.x, lane = tid & 31, wn = tid >> 5;
    const uint32_t wb = sb + WB_OFF + wn * 2 * WBUF;
    float acc[4][4][4];

    // ---- per-CTA init: q-halves of g_zp / g_zpb from z (p written by it0 s4)
    #pragma unroll 1
    for (int i = tid; i < NMT * 16 * 128; i += 256) {
        const int r = i >> 7, c4 = (i & 127) << 2;
        const float4 zv = *(const float4*)&z[(size_t)(m0 + r) * DIMQ + c4];
        const size_t oq = (size_t)(m0 + r) * ZPD + c4;
        *(float4*)&g_zp[oq] = zv;
        __nv_bfloat162 b01 = pack_bf2(zv.x, zv.y), b23 = pack_bf2(zv.z, zv.w);
        *(uint2*)&g_zpb[oq] = make_uint2(*(uint32_t*)&b01, *(uint32_t*)&b23);
    }
    __syncthreads();   // publish stores before stage-1 cp.async reads them

    // prime the chain: it0 stage1's B chunk0 (W1t, cOff=0)
    fillB_warp(wb, g_W1t, ZPD, wn * 32, 0, lane);
    cp_commit();

    #pragma unroll 1
    for (int it = 0; it < 8; it++) {
        const int call = it - (it / 3) * 3;
        const int qpOff   = (call == 1) ? DIMQ : 0;
        const int colBase = (call == 1) ? 0 : DIMQ;
        const float coef  = (call == 1) ? DTC : -0.5f * DTC;
        const int rec = (it == 0) ? 0 : ((call == 2) ? 0 : 1);   // 0 = q-half, 1 = p-half
        const int cOff = rec ? DIMQ : 0;
        const bool last = (it == 7);
        const int cOffN = (((it + 1) % 3) == 2) ? 0 : DIMQ;      // next it's stage-1 half

        // Stage 1 (half K): fresh = zp_half @ W1_half   [chains B -> W2t]
        stage1_gemm<NMT>(sb, g_zpb + (size_t)m0 * ZPD + cOff, g_W1t + cOff,
                         g_W2t, acc, tid);
        {
            float* recS = rec ? g_Sp : g_Sq;
            const float* othS = rec ? g_Sq : g_Sp;      // it==0: unused (Sp==0)
            const bool useOth = (it != 0);
            EPI_BEGIN(NMT)
                const size_t o = (size_t)(m0 + m) * HID + n;
                if (!last) *(float2*)(recS + o) = make_float2(v0, v1);
                float c0 = 0.f, c1 = 0.f;
                if (useOth) { const float2 cc = *(const float2*)(othS + o); c0 = cc.x; c1 = cc.y; }
                const float t0 = tanh_fast(v0 + c0 + __ldg(b1 + n));
                const float t1 = tanh_fast(v1 + c1 + __ldg(b1 + n + 1));
                *(__nv_bfloat162*)(smem + X_OFF + m * XPITCH + n * 2) = pack_bf2(t0, t1);
            EPI_END
        }
        __syncthreads();

        // Stage 2: d2 = (1 - tanh(h1@W2 + b2)^2) * W3 -> Y   [chains B -> W2d]
        gemm_res<NMT>(sb, X_OFF, g_W2t, g_W2d, HID, acc, lane, wn);
        EPI_BEGIN(NMT)
            const float t0 = tanh_fast(v0 + __ldg(b2 + n));
            const float t1 = tanh_fast(v1 + __ldg(b2 + n + 1));
            const float r0 = (1.0f - t0 * t0) * __ldg(W3 + n);
            const float r1 = (1.0f - t1 * t1) * __ldg(W3 + n + 1);
            *(__nv_bfloat162*)(smem + Y_OFF + m * XPITCH + n * 2) = pack_bf2(r0, r1);
        EPI_END
        __syncthreads();

        // Stage 3: d1 = (d2 @ W2^T) * (1 - h1^2) -> X in-place   [chains -> W1d p0]
        gemm_res<NMT>(sb, Y_OFF, g_W2d, g_W1d + (size_t)qpOff * HID, HID, acc, lane, wn);
        EPI_BEGIN(NMT)
            __nv_bfloat162* xp = (__nv_bfloat162*)(smem + X_OFF + m * XPITCH + n * 2);
            const __nv_bfloat162 hh = *xp;
            const float h0 = __bfloat162float(hh.x), h1v = __bfloat162float(hh.y);
            *xp = pack_bf2(v0 * (1.0f - h0 * h0), v1 * (1.0f - h1v * h1v));
        EPI_END
        __syncthreads();

        // Stage 4: g-half = d1 @ W1[qpOff..]^T, fused leapfrog zp update.
        #pragma unroll 1
        for (int pass = 0; pass < 2; pass++) {
            const __nv_bfloat16* Wcur = g_W1d + (size_t)(qpOff + pass * 256) * HID;
            const __nv_bfloat16* Wnxt = (pass == 0)
                ? g_W1d + (size_t)(qpOff + 256) * HID    // this stage's pass 2
                : g_W1t + cOffN;                          // next it's stage 1
            const int nstride = (pass == 0) ? HID : ZPD;
            gemm_res<NMT>(sb, X_OFF, Wcur, Wnxt, nstride, acc, lane, wn);
            if (last) {
                EPI_BEGIN(NMT)
                    const size_t o = (size_t)(m0 + m) * ZPD + pass * 256 + n;   // colBase = 0
                    float2 z2 = *(float2*)(g_zp + o);
                    z2.x += coef * v0;
                    z2.y += coef * v1;
                    *(float2*)(out + (size_t)(m0 + m) * DIMQ + pass * 256 + n) = z2;
                EPI_END
            } else if (it == 0) {
                // p == 0 before the first half-kick: pure write, no g_zp read
                EPI_BEGIN(NMT)
                    const size_t o = (size_t)(m0 + m) * ZPD + colBase + pass * 256 + n;
                    const float zx = coef * v0, zy = coef * v1;
                    *(float2*)(g_zp + o) = make_float2(zx, zy);
                    *(__nv_bfloat162*)(g_zpb + o) = pack_bf2(zx, zy);
                EPI_END
            } else {
                EPI_BEGIN(NMT)
                    const size_t o = (size_t)(m0 + m) * ZPD + colBase + pass * 256 + n;
                    float2 z2 = *(float2*)(g_zp + o);
                    z2.x += coef * v0;
                    z2.y += coef * v1;
                    *(float2*)(g_zp + o) = z2;
                    *(__nv_bfloat162*)(g_zpb + o) = pack_bf2(z2.x, z2.y);
                EPI_END
            }
        }
        __syncthreads();   // call boundary: zp/zpb visible to next stage 1
    }
}

__global__ void __launch_bounds__(256, 2) leapfrog_all(
    const float* __restrict__ z,
    const float* __restrict__ b1, const float* __restrict__ b2,
    const float* __restrict__ W3, float* __restrict__ out)
{
    extern __shared__ char smem[];
    const uint32_t sb = smem_u32(smem);
    const int bx = blockIdx.x;
    if (bx < N64CTAS) {
        leapfrog_body<4>(sb, smem, bx * 64, z, b1, b2, W3, out);
    } else {
        leapfrog_body<3>(sb, smem, N64CTAS * 64 + (bx - N64CTAS) * 48, z, b1, b2, W3, out);
    }
}

// ---------------- small kernels ----------------
__global__ void __launch_bounds__(256) prep_weights(const float* __restrict__ W1,
                                                    const float* __restrict__ W2)
{
    const int idx = blockIdx.x * 256 + threadIdx.x;     // 0 .. 262143
    {
        const int k = idx >> 8, n = idx & 255;
        const __nv_bfloat16 v = __float2bfloat16_rn(W1[idx]);
        g_W1d[idx] = v;
        g_W1t[n * ZPD + k] = v;
    }
    if (idx < HID * HID) {
        const int k = idx >> 8, n = idx & 255;
        const __nv_bfloat16 v = __float2bfloat16_rn(W2[idx]);
        g_W2d[idx] = v;
        g_W2t[n * HID + k] = v;
    }
}

// ---------------- launcher ----------------
extern "C" void kernel_launch(void* const* d_in, const int* in_sizes, int n_in,
                              void* d_out, int out_size)
{
    const float* z  = (const float*)d_in[0];
    const float* W1 = (const float*)d_in[1];
    const float* b1 = (const float*)d_in[2];
    const float* W2 = (const float*)d_in[3];
    const float* b2 = (const float*)d_in[4];
    const float* W3 = (const float*)d_in[5];
    // d_in[6] = b3: constant, no gradient contribution.
    float* out = (float*)d_out;

    cudaFuncSetAttribute(leapfrog_all, cudaFuncAttributeMaxDynamicSharedMemorySize, SMEM_SZ);

    const dim3 blk(256);
    prep_weights<<<ZPD * HID / 256, blk>>>(W1, W2);
    leapfrog_all<<<NGRID, blk, SMEM_SZ>>>(z, b1, b2, W3, out);
}

// round 16
// speedup vs baseline: 1.9223x; 1.0621x over previous
#include <cuda_runtime.h>
#include <cuda_bf16.h>
#include <stdint.h>

#define BATCH 16384
#define DIMQ  512
#define ZPD   1024
#define HID   256
#define DTC   0.1f

// grid: 136 CTAs x 64 rows + 160 CTAs x 48 rows = 296 CTAs = 2 x 148 SMs
#define N64CTAS 136
#define NGRID   296

// X/Y: 512B pitch + XOR swizzle (byte ^= (m&7)<<4)  -> conflict-free ldsm/stores
#define X_OFF 0
#define XSZ   (64 * 512)                  // 32768
#define Y_OFF XSZ                         // d2; stage-1 A ring overlay (6 x 4096)
#define ASLOT 4096                        // 64 rows x 64B (swizzled)
#define WB_OFF (2 * XSZ)                  // 65536: per-warp B triple buffers
#define WBUF 2048                         // 32 rows x 64B (swizzled)
#define SMEM_SZ (WB_OFF + 8 * 3 * WBUF)   // 114688 -> 2 CTAs/SM

// ---------------- device globals (no allocs allowed) ----------------
__device__ float         g_zp [BATCH * ZPD];     // fp32 master [q|p]
__device__ __nv_bfloat16 g_zpb[BATCH * ZPD];     // bf16 mirror (MMA operand)
__device__ float         g_Sq [BATCH * HID];     // cache: q @ W1[:512]
__device__ float         g_Sp [BATCH * HID];     // cache: p @ W1[512:]
__device__ __nv_bfloat16 g_W1t[HID * ZPD];       // W1^T [256][1024]
__device__ __nv_bfloat16 g_W1d[ZPD * HID];       // W1   [1024][256]
__device__ __nv_bfloat16 g_W2t[HID * HID];       // W2^T
__device__ __nv_bfloat16 g_W2d[HID * HID];       // W2

// ---------------- helpers ----------------
__device__ __forceinline__ uint32_t smem_u32(const void* p) {
    uint32_t a;
    asm("{ .reg .u64 t; cvta.to.shared.u64 t, %1; cvt.u32.u64 %0, t; }" : "=r"(a) : "l"(p));
    return a;
}
__device__ __forceinline__ float tanh_fast(float x) {
    float y; asm("tanh.approx.f32 %0, %1;" : "=f"(y) : "f"(x)); return y;
}
__device__ __forceinline__ void cp16(uint32_t s, const void* g) {
    asm volatile("cp.async.cg.shared.global [%0], [%1], 16;" :: "r"(s), "l"(g) : "memory");
}
__device__ __forceinline__ void cp_commit() {
    asm volatile("cp.async.commit_group;" ::: "memory");
}
__device__ __forceinline__ void ldsm4(uint32_t* r, uint32_t a) {
    asm volatile("ldmatrix.sync.aligned.m8n8.x4.shared.b16 {%0,%1,%2,%3}, [%4];"
                 : "=r"(r[0]), "=r"(r[1]), "=r"(r[2]), "=r"(r[3]) : "r"(a));
}
__device__ __forceinline__ void mma16816(float* c, const uint32_t* a, const uint32_t* b) {
    asm volatile("mma.sync.aligned.m16n8k16.row.col.f32.bf16.bf16.f32 "
                 "{%0,%1,%2,%3}, {%4,%5,%6,%7}, {%8,%9}, {%0,%1,%2,%3};"
                 : "+f"(c[0]), "+f"(c[1]), "+f"(c[2]), "+f"(c[3])
                 : "r"(a[0]), "r"(a[1]), "r"(a[2]), "r"(a[3]), "r"(b[0]), "r"(b[1]));
}
__device__ __forceinline__ __nv_bfloat162 pack_bf2(float a, float b) {
    return __halves2bfloat162(__float2bfloat16_rn(a), __float2bfloat16_rn(b));
}
// 64B-row swizzle: 16B-unit j at row r -> j ^ ((r>>1)&3)
__device__ __forceinline__ uint32_t sw64(int row, int j) {
    return row * 64 + ((j ^ ((row >> 1) & 3)) << 4);
}
// X/Y 512B-row swizzle: byte b at row m -> b ^ ((m&7)<<4)   (b must be 4B-mult)
__device__ __forceinline__ uint32_t swXY(int m, int b) {
    return m * 512 + (b ^ ((m & 7) << 4));
}

#define ZERO_ACC(acc, NMT)                                                      \
    _Pragma("unroll") for (int _i = 0; _i < NMT; _i++)                          \
    _Pragma("unroll") for (int _j = 0; _j < 4; _j++)                            \
    _Pragma("unroll") for (int _d = 0; _d < 4; _d++) (acc)[_i][_j][_d] = 0.f;

// consume one k32 chunk.  AMODE 0: A from a 64B-row swizzled ring slot.
// AMODE 1: A from X/Y (512B pitch swizzled), k-offset = cA*64 bytes.
template <int NMT, int AMODE>
__device__ __forceinline__ void consume_k32(
    uint32_t abase, int cA, uint32_t bbase,
    float (&acc)[4][4][4], int lane)
{
    #pragma unroll
    for (int kt = 0; kt < 2; kt++) {
        uint32_t a[NMT][4], b[2][4];
        #pragma unroll
        for (int mt = 0; mt < NMT; mt++) {
            const int ra = mt * 16 + (lane & 15);
            if (AMODE == 0)
                ldsm4(a[mt], abase + sw64(ra, (lane >> 4) + kt * 2));
            else
                ldsm4(a[mt], abase + swXY(ra, ((lane >> 4) << 4) + kt * 32 + cA * 64));
        }
        #pragma unroll
        for (int p = 0; p < 2; p++) {
            const int rb = p * 16 + ((lane >> 4) << 3) + (lane & 7);
            ldsm4(b[p], bbase + sw64(rb, ((lane >> 3) & 1) + kt * 2));
        }
        #pragma unroll
        for (int mt = 0; mt < NMT; mt++)
            #pragma unroll
            for (int p = 0; p < 2; p++) {
                mma16816(acc[mt][2 * p],     a[mt], &b[p][0]);
                mma16816(acc[mt][2 * p + 1], a[mt], &b[p][2]);
            }
    }
}

// fill warp-private B slot: 32 weight rows x one k32 chunk (swizzled 64B rows)
__device__ __forceinline__ void fillB_warp(uint32_t stg, const __nv_bfloat16* __restrict__ W,
                                           int stride, int n0w, int c, int lane)
{
    #pragma unroll
    for (int r = 0; r < 4; r++) {
        const int u = r * 32 + lane;
        const int row = u >> 2, ch = u & 3;
        cp16(stg + sw64(row, ch), W + (size_t)(n0w + row) * stride + c * 32 + ch * 8);
    }
}

// ---------------------------------------------------------------------------
// Stage 1 (half K): acc = zp_half[M x 512] @ W1t_half^T.   Buffer phase 0.
// ENTRY: B(0) in buf0, B(1) in buf1 (2 pending groups), then prologue commits
// A(0,1) and A(2,3).  Per iter: wait (c==0 ? 1 : 3) -> barrier -> commit
// B(c+2) -> commit A(c+4) -> consume(c).  Last two iters chain the NEXT
// segment's B chunks 0,1.  A ring: 6 slots, distance 4, barrier every 2 iters.
// ---------------------------------------------------------------------------
template <int NMT>
__device__ __forceinline__ void stage1_gemm(
    uint32_t sb, const __nv_bfloat16* __restrict__ Agm,
    const __nv_bfloat16* __restrict__ Bgm,      // W1t + cOff
    const __nv_bfloat16* __restrict__ Bnext,    // next segment's weights (stride HID)
    float (&acc)[4][4][4], int tid)
{
    const int lane = tid & 31, wn = tid >> 5;
    const uint32_t wb = sb + WB_OFF + wn * 3 * WBUF;
    ZERO_ACC(acc, NMT);

    auto fillA = [&](int s, int c) {
        if (tid < NMT * 64) {   // NMT*16 rows x 4 x 16B units, 1/thread
            const int row = tid >> 2, ch = tid & 3;
            cp16(sb + Y_OFF + s * ASLOT + sw64(row, ch),
                 Agm + (size_t)row * ZPD + c * 32 + ch * 8);
        }
    };

    fillA(0, 0); fillA(1, 1); cp_commit();
    fillA(2, 2); fillA(3, 3); cp_commit();

    int bc = 0, bf = 2;
    #pragma unroll 1
    for (int c = 0; c < 16; c++) {
        if (c == 0) asm volatile("cp.async.wait_group 1;" ::: "memory");
        else        asm volatile("cp.async.wait_group 3;" ::: "memory");
        if ((c & 1) == 0) __syncthreads();
        else              __syncwarp();
        if (c + 2 < 16) fillB_warp(wb + bf * WBUF, Bgm, ZPD, wn * 32, c + 2, lane);
        else            fillB_warp(wb + bf * WBUF, Bnext, HID, wn * 32, c - 14, lane);
        cp_commit();
        if (c + 4 < 16) fillA((c + 4) % 6, c + 4);
        cp_commit();
        consume_k32<NMT, 0>(sb + Y_OFF + (c % 6) * ASLOT, 0, wb + bc * WBUF, acc, lane);
        bc = (bc == 2) ? 0 : bc + 1;
        bf = (bf == 2) ? 0 : bf + 1;
    }
}

// ---------------------------------------------------------------------------
// Stages 2-4: A resident in X/Y, B warp-local TRIPLE buffer (distance 2).
// ENTRY: B(0), B(1) pending in bufs P, (P+1)%3.  Last two iters chain the
// next segment's B chunks 0,1.  NO CTA barriers.
// ---------------------------------------------------------------------------
template <int NMT, int P>
__device__ __forceinline__ void gemm_res(
    uint32_t sb, uint32_t aOff, const __nv_bfloat16* __restrict__ W,
    const __nv_bfloat16* __restrict__ Wnext, int nextStride,
    float (&acc)[4][4][4], int lane, int wn)
{
    ZERO_ACC(acc, NMT);
    const uint32_t wb = sb + WB_OFF + wn * 3 * WBUF;
    const int n0w = wn * 32;

    int bc = P, bf = (P + 2) % 3;
    #pragma unroll 1
    for (int c = 0; c < 8; c++) {
        if (c + 2 < 8) fillB_warp(wb + bf * WBUF, W, HID, n0w, c + 2, lane);
        else           fillB_warp(wb + bf * WBUF, Wnext, nextStride, n0w, c - 6, lane);
        cp_commit();
        asm volatile("cp.async.wait_group 2;" ::: "memory");
        __syncwarp();
        consume_k32<NMT, 1>(sb + aOff, c, wb + bc * WBUF, acc, lane);
        bc = (bc == 2) ? 0 : bc + 1;
        bf = (bf == 2) ? 0 : bf + 1;
    }
}

#define EPI_BEGIN(NMT)                                                          \
    _Pragma("unroll") for (int mt = 0; mt < NMT; mt++)                          \
    _Pragma("unroll") for (int i2 = 0; i2 < 2; i2++) {                          \
        const int m = mt * 16 + i2 * 8 + (lane >> 2);                           \
        _Pragma("unroll") for (int nt = 0; nt < 4; nt++) {                      \
            const int n = wn * 32 + nt * 8 + 2 * (lane & 3);                    \
            const float v0 = acc[mt][nt][i2 * 2], v1 = acc[mt][nt][i2 * 2 + 1];
#define EPI_END }}

// ---------------------------------------------------------------------------
// Leapfrog body: one CTA owns NMT*16 batch rows.  Per-CTA zp init, it8 dead-
// code eliminated, it7 writes q straight to out.  B chained two-deep across
// ALL segment boundaries with compile-time buffer phases (0,1,0,2,1).
// ---------------------------------------------------------------------------
template <int NMT>
__device__ __forceinline__ void leapfrog_body(
    uint32_t sb, char* smem, int m0, const float* __restrict__ z,
    const float* __restrict__ b1, const float* __restrict__ b2,
    const float* __restrict__ W3, float* __restrict__ out)
{
    const int tid = threadIdx.x, lane = tid & 31, wn = tid >> 5;
    const uint32_t wb = sb + WB_OFF + wn * 3 * WBUF;
    float acc[4][4][4];

    // ---- per-CTA init: q-halves of g_zp / g_zpb from z (p written by it0 s4)
    #pragma unroll 1
    for (int i = tid; i < NMT * 16 * 128; i += 256) {
        const int r = i >> 7, c4 = (i & 127) << 2;
        const float4 zv = *(const float4*)&z[(size_t)(m0 + r) * DIMQ + c4];
        const size_t oq = (size_t)(m0 + r) * ZPD + c4;
        *(float4*)&g_zp[oq] = zv;
        __nv_bfloat162 b01 = pack_bf2(zv.x, zv.y), b23 = pack_bf2(zv.z, zv.w);
        *(uint2*)&g_zpb[oq] = make_uint2(*(uint32_t*)&b01, *(uint32_t*)&b23);
    }
    __syncthreads();   // publish stores before stage-1 cp.async reads them

    // prime the chain: it0 stage1's B chunks 0,1 (W1t, cOff=0) -> bufs 0,1
    fillB_warp(wb + 0 * WBUF, g_W1t, ZPD, wn * 32, 0, lane); cp_commit();
    fillB_warp(wb + 1 * WBUF, g_W1t, ZPD, wn * 32, 1, lane); cp_commit();

    #pragma unroll 1
    for (int it = 0; it < 8; it++) {
        const int call = it - (it / 3) * 3;
        const int qpOff   = (call == 1) ? DIMQ : 0;
        const int colBase = (call == 1) ? 0 : DIMQ;
        const float coef  = (call == 1) ? DTC : -0.5f * DTC;
        const int rec = (it == 0) ? 0 : ((call == 2) ? 0 : 1);   // 0 = q-half, 1 = p-half
        const int cOff = rec ? DIMQ : 0;
        const bool last = (it == 7);
        const int cOffN = (((it + 1) % 3) == 2) ? 0 : DIMQ;      // next it's stage-1 half

        // Stage 1 (half K): fresh = zp_half @ W1_half   [chains B -> W2t x2]
        stage1_gemm<NMT>(sb, g_zpb + (size_t)m0 * ZPD + cOff, g_W1t + cOff,
                         g_W2t, acc, tid);
        {
            float* recS = rec ? g_Sp : g_Sq;
            const float* othS = rec ? g_Sq : g_Sp;      // it==0: unused (Sp==0)
            const bool useOth = (it != 0);
            EPI_BEGIN(NMT)
                const size_t o = (size_t)(m0 + m) * HID + n;
                if (!last) *(float2*)(recS + o) = make_float2(v0, v1);
                float c0 = 0.f, c1 = 0.f;
                if (useOth) { const float2 cc = *(const float2*)(othS + o); c0 = cc.x; c1 = cc.y; }
                const float t0 = tanh_fast(v0 + c0 + __ldg(b1 + n));
                const float t1 = tanh_fast(v1 + c1 + __ldg(b1 + n + 1));
                *(__nv_bfloat162*)(smem + X_OFF + swXY(m, n * 2)) = pack_bf2(t0, t1);
            EPI_END
        }
        __syncthreads();

        // Stage 2 (phase 1): d2 = (1 - tanh(h1@W2 + b2)^2) * W3 -> Y   [chains -> W2d]
        gemm_res<NMT, 1>(sb, X_OFF, g_W2t, g_W2d, HID, acc, lane, wn);
        EPI_BEGIN(NMT)
            const float t0 = tanh_fast(v0 + __ldg(b2 + n));
            const float t1 = tanh_fast(v1 + __ldg(b2 + n + 1));
            const float r0 = (1.0f - t0 * t0) * __ldg(W3 + n);
            const float r1 = (1.0f - t1 * t1) * __ldg(W3 + n + 1);
            *(__nv_bfloat162*)(smem + Y_OFF + swXY(m, n * 2)) = pack_bf2(r0, r1);
        EPI_END
        __syncthreads();

        // Stage 3 (phase 0): d1 = (d2 @ W2^T) * (1 - h1^2) -> X in-place   [chains -> W1d p0]
        gemm_res<NMT, 0>(sb, Y_OFF, g_W2d, g_W1d + (size_t)qpOff * HID, HID, acc, lane, wn);
        EPI_BEGIN(NMT)
            __nv_bfloat162* xp = (__nv_bfloat162*)(smem + X_OFF + swXY(m, n * 2));
            const __nv_bfloat162 hh = *xp;
            const float h0 = __bfloat162float(hh.x), h1v = __bfloat162float(hh.y);
            *xp = pack_bf2(v0 * (1.0f - h0 * h0), v1 * (1.0f - h1v * h1v));
        EPI_END
        __syncthreads();

        // Stage 4 (phases 2, 1): g-half = d1 @ W1[qpOff..]^T, fused zp update.
        #pragma unroll 1
        for (int pass = 0; pass < 2; pass++) {
            const __nv_bfloat16* Wcur = g_W1d + (size_t)(qpOff + pass * 256) * HID;
            const __nv_bfloat16* Wnxt = (pass == 0)
                ? g_W1d + (size_t)(qpOff + 256) * HID    // this stage's pass 2
                : g_W1t + cOffN;                          // next it's stage 1
            const int nstride = (pass == 0) ? HID : ZPD;
            if (pass == 0) gemm_res<NMT, 2>(sb, X_OFF, Wcur, Wnxt, nstride, acc, lane, wn);
            else           gemm_res<NMT, 1>(sb, X_OFF, Wcur, Wnxt, nstride, acc, lane, wn);
            if (last) {
                EPI_BEGIN(NMT)
                    const size_t o = (size_t)(m0 + m) * ZPD + pass * 256 + n;   // colBase = 0
                    float2 z2 = *(float2*)(g_zp + o);
                    z2.x += coef * v0;
                    z2.y += coef * v1;
                    *(float2*)(out + (size_t)(m0 + m) * DIMQ + pass * 256 + n) = z2;
                EPI_END
            } else if (it == 0) {
                // p == 0 before the first half-kick: pure write, no g_zp read
                EPI_BEGIN(NMT)
                    const size_t o = (size_t)(m0 + m) * ZPD + colBase + pass * 256 + n;
                    const float zx = coef * v0, zy = coef * v1;
                    *(float2*)(g_zp + o) = make_float2(zx, zy);
                    *(__nv_bfloat162*)(g_zpb + o) = pack_bf2(zx, zy);
                EPI_END
            } else {
                EPI_BEGIN(NMT)
                    const size_t o = (size_t)(m0 + m) * ZPD + colBase + pass * 256 + n;
                    float2 z2 = *(float2*)(g_zp + o);
                    z2.x += coef * v0;
                    z2.y += coef * v1;
                    *(float2*)(g_zp + o) = z2;
                    *(__nv_bfloat162*)(g_zpb + o) = pack_bf2(z2.x, z2.y);
                EPI_END
            }
        }
        __syncthreads();   // call boundary: zp/zpb visible to next stage 1
    }
}

__global__ void __launch_bounds__(256, 2) leapfrog_all(
    const float* __restrict__ z,
    const float* __restrict__ b1, const float* __restrict__ b2,
    const float* __restrict__ W3, float* __restrict__ out)
{
    extern __shared__ char smem[];
    const uint32_t sb = smem_u32(smem);
    const int bx = blockIdx.x;
    if (bx < N64CTAS) {
        leapfrog_body<4>(sb, smem, bx * 64, z, b1, b2, W3, out);
    } else {
        leapfrog_body<3>(sb, smem, N64CTAS * 64 + (bx - N64CTAS) * 48, z, b1, b2, W3, out);
    }
}

// ---------------- small kernels ----------------
__global__ void __launch_bounds__(256) prep_weights(const float* __restrict__ W1,
                                                    const float* __restrict__ W2)
{
    const int idx = blockIdx.x * 256 + threadIdx.x;     // 0 .. 262143
    {
        const int k = idx >> 8, n = idx & 255;
        const __nv_bfloat16 v = __float2bfloat16_rn(W1[idx]);
        g_W1d[idx] = v;
        g_W1t[n * ZPD + k] = v;
    }
    if (idx < HID * HID) {
        const int k = idx >> 8, n = idx & 255;
        const __nv_bfloat16 v = __float2bfloat16_rn(W2[idx]);
        g_W2d[idx] = v;
        g_W2t[n * HID + k] = v;
    }
}

// ---------------- launcher ----------------
extern "C" void kernel_launch(void* const* d_in, const int* in_sizes, int n_in,
                              void* d_out, int out_size)
{
    const float* z  = (const float*)d_in[0];
    const float* W1 = (const float*)d_in[1];
    const float* b1 = (const float*)d_in[2];
    const float* W2 = (const float*)d_in[3];
    const float* b2 = (const float*)d_in[4];
    const float* W3 = (const float*)d_in[5];
    // d_in[6] = b3: constant, no gradient contribution.
    float* out = (float*)d_out;

    cudaFuncSetAttribute(leapfrog_all, cudaFuncAttributeMaxDynamicSharedMemorySize, SMEM_SZ);

    const dim3 blk(256);
    prep_weights<<<ZPD * HID / 256, blk>>>(W1, W2);
    leapfrog_all<<<NGRID, blk, SMEM_SZ>>>(z, b1, b2, W3, out);
}